// round 2
// baseline (speedup 1.0000x reference)
#include <cuda_runtime.h>

#define B_    8
#define N_    2048
#define D_    512
#define H_    8
#define DH_   64
#define ROWS_ (B_ * N_)   // 16384

// Scratch (device globals — no allocations allowed in kernel_launch).
__device__ float g_xn[(size_t)ROWS_ * D_];   // LayerNorm output [16384, 512]
__device__ float g_q[(size_t)ROWS_ * D_];    // [b][h][n][dh]
__device__ float g_k[(size_t)ROWS_ * D_];    // [b][h][n][dh]
__device__ float g_v[(size_t)ROWS_ * D_];    // [b][h][n][dh]
__device__ float g_att[(size_t)ROWS_ * D_];  // attention out, [b][n][h*dh]

// ---------------------------------------------------------------------------
// LayerNorm: one row (512 floats) per 128-thread block, float4 per thread.
// ---------------------------------------------------------------------------
__global__ __launch_bounds__(128) void ln_kernel(const float* __restrict__ x,
                                                 const float* __restrict__ gamma,
                                                 const float* __restrict__ beta) {
    const int row = blockIdx.x;
    const int t = threadIdx.x;
    const float4 v = reinterpret_cast<const float4*>(x + (size_t)row * D_)[t];
    float s  = v.x + v.y + v.z + v.w;
    float ss = v.x * v.x + v.y * v.y + v.z * v.z + v.w * v.w;
#pragma unroll
    for (int o = 16; o; o >>= 1) {
        s  += __shfl_xor_sync(0xffffffffu, s, o);
        ss += __shfl_xor_sync(0xffffffffu, ss, o);
    }
    __shared__ float sh[4], sh2[4];
    if ((t & 31) == 0) { sh[t >> 5] = s; sh2[t >> 5] = ss; }
    __syncthreads();
    s  = sh[0] + sh[1] + sh[2] + sh[3];
    ss = sh2[0] + sh2[1] + sh2[2] + sh2[3];
    const float mean = s * (1.0f / D_);
    const float var  = ss * (1.0f / D_) - mean * mean;
    const float rstd = rsqrtf(var + 1e-6f);
    const float4 g4 = reinterpret_cast<const float4*>(gamma)[t];
    const float4 b4 = reinterpret_cast<const float4*>(beta)[t];
    float4 r;
    r.x = (v.x - mean) * rstd * g4.x + b4.x;
    r.y = (v.y - mean) * rstd * g4.y + b4.y;
    r.z = (v.z - mean) * rstd * g4.z + b4.z;
    r.w = (v.w - mean) * rstd * g4.w + b4.w;
    reinterpret_cast<float4*>(g_xn + (size_t)row * D_)[t] = r;
}

// ---------------------------------------------------------------------------
// QKV GEMM: C[16384,1536] = xn[16384,512] @ w_qkv[1536,512]^T
// 128x128x8 tiles, 256 threads, 8x8 microtile. Epilogue scatters into
// q/k/v in [b][h][n][dh] layout.
// ---------------------------------------------------------------------------
__global__ __launch_bounds__(256) void qkv_gemm_kernel(const float* __restrict__ W) {
    __shared__ __align__(16) float As[8 * 132];
    __shared__ __align__(16) float Ws[8 * 132];
    const int t  = threadIdx.x;
    const int bm = blockIdx.y * 128;
    const int bn = blockIdx.x * 128;
    const int ty = t >> 4, tx = t & 15;
    const int lr = t >> 1;          // load row 0..127
    const int ls = (t & 1) * 4;     // k offset 0 or 4
    const float* Ap = g_xn + (size_t)(bm + lr) * 512 + ls;
    const float* Wp = W + (size_t)(bn + lr) * 512 + ls;

    float acc[8][8];
#pragma unroll
    for (int i = 0; i < 8; i++)
#pragma unroll
        for (int j = 0; j < 8; j++) acc[i][j] = 0.0f;

    for (int k0 = 0; k0 < 512; k0 += 8) {
        const float4 av = *reinterpret_cast<const float4*>(Ap + k0);
        const float4 wv = *reinterpret_cast<const float4*>(Wp + k0);
        __syncthreads();
        As[(ls + 0) * 132 + lr] = av.x;
        As[(ls + 1) * 132 + lr] = av.y;
        As[(ls + 2) * 132 + lr] = av.z;
        As[(ls + 3) * 132 + lr] = av.w;
        Ws[(ls + 0) * 132 + lr] = wv.x;
        Ws[(ls + 1) * 132 + lr] = wv.y;
        Ws[(ls + 2) * 132 + lr] = wv.z;
        Ws[(ls + 3) * 132 + lr] = wv.w;
        __syncthreads();
#pragma unroll
        for (int k = 0; k < 8; k++) {
            const float4 a0 = *reinterpret_cast<const float4*>(&As[k * 132 + ty * 8]);
            const float4 a1 = *reinterpret_cast<const float4*>(&As[k * 132 + ty * 8 + 4]);
            const float4 b0 = *reinterpret_cast<const float4*>(&Ws[k * 132 + tx * 8]);
            const float4 b1 = *reinterpret_cast<const float4*>(&Ws[k * 132 + tx * 8 + 4]);
            const float a[8] = {a0.x, a0.y, a0.z, a0.w, a1.x, a1.y, a1.z, a1.w};
            const float b[8] = {b0.x, b0.y, b0.z, b0.w, b1.x, b1.y, b1.z, b1.w};
#pragma unroll
            for (int i = 0; i < 8; i++)
#pragma unroll
                for (int j = 0; j < 8; j++) acc[i][j] += a[i] * b[j];
        }
    }

    // epilogue: whole block lives in one of q/k/v (128 | 512)
    const int which = bn >> 9;
    float* dst = (which == 0) ? g_q : ((which == 1) ? g_k : g_v);
    const int cb = (bn & 511) + tx * 8;   // column within the 512-wide segment
    const int h  = cb >> 6;
    const int d0 = cb & 63;               // multiple of 8 -> two float4 stores
#pragma unroll
    for (int i = 0; i < 8; i++) {
        const int m = bm + ty * 8 + i;
        const int b = m >> 11, n = m & 2047;
        float* p = dst + ((size_t)(b * H_ + h) * N_ + n) * DH_ + d0;
        *reinterpret_cast<float4*>(p) =
            make_float4(acc[i][0], acc[i][1], acc[i][2], acc[i][3]);
        *reinterpret_cast<float4*>(p + 4) =
            make_float4(acc[i][4], acc[i][5], acc[i][6], acc[i][7]);
    }
}

// ---------------------------------------------------------------------------
// Flash attention: grid (32 q-tiles, 64 bh), 256 threads, Br=Bc=64, Dh=64.
// Q, K, P tiles stored TRANSPOSED (reduction-dim-major) with XOR swizzle
//   addr(r, c) = r*64 + (c ^ (r & 28))
// so both microtile operands of the two inner GEMM loops are LDS.128.
// Stores land with <=2-way bank conflicts; loads are chunk permutations
// (conflict-free / broadcast).
// ---------------------------------------------------------------------------
#define SWI(r, c) ((r) * 64 + ((c) ^ ((r) & 28)))
#define ATTN_SMEM (4 * 64 * 64 * sizeof(float))   // Qt + Kt + V + Pt = 64 KB

__global__ __launch_bounds__(256) void attn_kernel() {
    extern __shared__ __align__(16) float sm[];
    float* Qs = sm;               // [d][m] swizzled, 64x64
    float* Ks = Qs + 64 * 64;     // [d][n] swizzled, 64x64
    float* Vs = Ks + 64 * 64;     // [c][d] row-major, 64x64
    float* Ps = Vs + 64 * 64;     // [c][m] swizzled, 64x64

    const int t  = threadIdx.x;
    const int ty = t >> 4, tx = t & 15;   // 16x16 thread grid, 4x4 microtile
    const int ty4 = ty * 4, tx4 = tx * 4;
    const int bh = blockIdx.y;
    const int q0 = blockIdx.x * 64;
    const float* Qg = g_q + (size_t)bh * N_ * DH_;
    const float* Kg = g_k + (size_t)bh * N_ * DH_;
    const float* Vg = g_v + (size_t)bh * N_ * DH_;

    // load Q tile, store transposed+swizzled: Qt[d][m]
#pragma unroll
    for (int it = 0; it < 4; it++) {
        const int i = t + it * 256;
        const int r = i >> 4, c4 = (i & 15) << 2;   // r = m, c4 = d base
        const float4 qv = *reinterpret_cast<const float4*>(Qg + (size_t)(q0 + r) * DH_ + c4);
        Qs[SWI(c4 + 0, r)] = qv.x;
        Qs[SWI(c4 + 1, r)] = qv.y;
        Qs[SWI(c4 + 2, r)] = qv.z;
        Qs[SWI(c4 + 3, r)] = qv.w;
    }

    float m_r[4], l_r[4], O[4][4];
#pragma unroll
    for (int i = 0; i < 4; i++) {
        m_r[i] = -1e30f; l_r[i] = 0.0f;
#pragma unroll
        for (int j = 0; j < 4; j++) O[i][j] = 0.0f;
    }
    __syncthreads();

    for (int kt = 0; kt < 32; kt++) {
        // load K transposed+swizzled, V row-major
#pragma unroll
        for (int it = 0; it < 4; it++) {
            const int i = t + it * 256;
            const int r = i >> 4, c4 = (i & 15) << 2;
            const float4 kv = *reinterpret_cast<const float4*>(Kg + (size_t)(kt * 64 + r) * DH_ + c4);
            Ks[SWI(c4 + 0, r)] = kv.x;
            Ks[SWI(c4 + 1, r)] = kv.y;
            Ks[SWI(c4 + 2, r)] = kv.z;
            Ks[SWI(c4 + 3, r)] = kv.w;
            const float4 vv = *reinterpret_cast<const float4*>(Vg + (size_t)(kt * 64 + r) * DH_ + c4);
            *reinterpret_cast<float4*>(Vs + r * 64 + c4) = vv;
        }
        __syncthreads();

        // S = Q K^T : both operands LDS.128 from transposed tiles
        float s[4][4];
#pragma unroll
        for (int i = 0; i < 4; i++)
#pragma unroll
            for (int j = 0; j < 4; j++) s[i][j] = 0.0f;
#pragma unroll 8
        for (int d = 0; d < 64; d++) {
            const float4 a4 = *reinterpret_cast<const float4*>(Qs + SWI(d, ty4));
            const float4 b4 = *reinterpret_cast<const float4*>(Ks + SWI(d, tx4));
            const float a[4] = {a4.x, a4.y, a4.z, a4.w};
            const float b[4] = {b4.x, b4.y, b4.z, b4.w};
#pragma unroll
            for (int i = 0; i < 4; i++)
#pragma unroll
                for (int j = 0; j < 4; j++) s[i][j] += a[i] * b[j];
        }
#pragma unroll
        for (int i = 0; i < 4; i++)
#pragma unroll
            for (int j = 0; j < 4; j++) s[i][j] *= 0.125f;

        // online softmax; rows ty4..+3 shared across 16 lanes (shfl group)
        float alpha[4];
#pragma unroll
        for (int i = 0; i < 4; i++) {
            float mx = fmaxf(fmaxf(s[i][0], s[i][1]), fmaxf(s[i][2], s[i][3]));
#pragma unroll
            for (int o = 8; o; o >>= 1) mx = fmaxf(mx, __shfl_xor_sync(0xffffffffu, mx, o));
            const float mn = fmaxf(m_r[i], mx);
            float rs = 0.0f;
#pragma unroll
            for (int j = 0; j < 4; j++) {
                const float p = __expf(s[i][j] - mn);
                s[i][j] = p;
                rs += p;
            }
#pragma unroll
            for (int o = 8; o; o >>= 1) rs += __shfl_xor_sync(0xffffffffu, rs, o);
            const float al = __expf(m_r[i] - mn);
            l_r[i] = l_r[i] * al + rs;
            m_r[i] = mn;
            alpha[i] = al;
        }

        // store P transposed+swizzled: Pt[c=n][m], STS.128 per column j
#pragma unroll
        for (int j = 0; j < 4; j++) {
            *reinterpret_cast<float4*>(Ps + SWI(tx4 + j, ty4)) =
                make_float4(s[0][j], s[1][j], s[2][j], s[3][j]);
        }
        __syncthreads();

        // O = O*alpha + P V : both operands LDS.128
#pragma unroll
        for (int i = 0; i < 4; i++)
#pragma unroll
            for (int j = 0; j < 4; j++) O[i][j] *= alpha[i];
#pragma unroll 8
        for (int c = 0; c < 64; c++) {
            const float4 p4 = *reinterpret_cast<const float4*>(Ps + SWI(c, ty4));
            const float4 v4 = *reinterpret_cast<const float4*>(Vs + c * 64 + tx4);
            const float p[4] = {p4.x, p4.y, p4.z, p4.w};
            const float v[4] = {v4.x, v4.y, v4.z, v4.w};
#pragma unroll
            for (int i = 0; i < 4; i++)
#pragma unroll
                for (int j = 0; j < 4; j++) O[i][j] += p[i] * v[j];
        }
        __syncthreads();
    }

    // normalize and write to g_att [b][n][h*64 + d]
    const int b = bh >> 3, h = bh & 7;
#pragma unroll
    for (int i = 0; i < 4; i++) {
        const float inv = 1.0f / l_r[i];
        const int n = q0 + ty4 + i;
        const float4 o4 = make_float4(O[i][0] * inv, O[i][1] * inv,
                                      O[i][2] * inv, O[i][3] * inv);
        *reinterpret_cast<float4*>(g_att + ((size_t)(b * N_ + n)) * D_ + h * DH_ + tx4) = o4;
    }
}

// ---------------------------------------------------------------------------
// Output projection: out[16384,512] = g_att @ w_proj[512,512]^T + b_proj
// ---------------------------------------------------------------------------
__global__ __launch_bounds__(256) void proj_gemm_kernel(const float* __restrict__ W,
                                                        const float* __restrict__ bias,
                                                        float* __restrict__ C) {
    __shared__ __align__(16) float As[8 * 132];
    __shared__ __align__(16) float Ws[8 * 132];
    const int t  = threadIdx.x;
    const int bm = blockIdx.y * 128;
    const int bn = blockIdx.x * 128;
    const int ty = t >> 4, tx = t & 15;
    const int lr = t >> 1;
    const int ls = (t & 1) * 4;
    const float* Ap = g_att + (size_t)(bm + lr) * 512 + ls;
    const float* Wp = W + (size_t)(bn + lr) * 512 + ls;

    float acc[8][8];
#pragma unroll
    for (int i = 0; i < 8; i++)
#pragma unroll
        for (int j = 0; j < 8; j++) acc[i][j] = 0.0f;

    for (int k0 = 0; k0 < 512; k0 += 8) {
        const float4 av = *reinterpret_cast<const float4*>(Ap + k0);
        const float4 wv = *reinterpret_cast<const float4*>(Wp + k0);
        __syncthreads();
        As[(ls + 0) * 132 + lr] = av.x;
        As[(ls + 1) * 132 + lr] = av.y;
        As[(ls + 2) * 132 + lr] = av.z;
        As[(ls + 3) * 132 + lr] = av.w;
        Ws[(ls + 0) * 132 + lr] = wv.x;
        Ws[(ls + 1) * 132 + lr] = wv.y;
        Ws[(ls + 2) * 132 + lr] = wv.z;
        Ws[(ls + 3) * 132 + lr] = wv.w;
        __syncthreads();
#pragma unroll
        for (int k = 0; k < 8; k++) {
            const float4 a0 = *reinterpret_cast<const float4*>(&As[k * 132 + ty * 8]);
            const float4 a1 = *reinterpret_cast<const float4*>(&As[k * 132 + ty * 8 + 4]);
            const float4 b0 = *reinterpret_cast<const float4*>(&Ws[k * 132 + tx * 8]);
            const float4 b1 = *reinterpret_cast<const float4*>(&Ws[k * 132 + tx * 8 + 4]);
            const float a[8] = {a0.x, a0.y, a0.z, a0.w, a1.x, a1.y, a1.z, a1.w};
            const float b[8] = {b0.x, b0.y, b0.z, b0.w, b1.x, b1.y, b1.z, b1.w};
#pragma unroll
            for (int i = 0; i < 8; i++)
#pragma unroll
                for (int j = 0; j < 8; j++) acc[i][j] += a[i] * b[j];
        }
    }

    const int c0 = bn + tx * 8;
    const float4 bs0 = *reinterpret_cast<const float4*>(bias + c0);
    const float4 bs1 = *reinterpret_cast<const float4*>(bias + c0 + 4);
#pragma unroll
    for (int i = 0; i < 8; i++) {
        const int m = bm + ty * 8 + i;
        float* p = C + (size_t)m * 512 + c0;
        *reinterpret_cast<float4*>(p) =
            make_float4(acc[i][0] + bs0.x, acc[i][1] + bs0.y,
                        acc[i][2] + bs0.z, acc[i][3] + bs0.w);
        *reinterpret_cast<float4*>(p + 4) =
            make_float4(acc[i][4] + bs1.x, acc[i][5] + bs1.y,
                        acc[i][6] + bs1.z, acc[i][7] + bs1.w);
    }
}

// ---------------------------------------------------------------------------
extern "C" void kernel_launch(void* const* d_in, const int* in_sizes, int n_in,
                              void* d_out, int out_size) {
    const float* x      = (const float*)d_in[0];
    const float* w_qkv  = (const float*)d_in[1];
    const float* w_proj = (const float*)d_in[2];
    const float* b_proj = (const float*)d_in[3];
    const float* gamma  = (const float*)d_in[4];
    const float* beta   = (const float*)d_in[5];
    float* out = (float*)d_out;

    ln_kernel<<<ROWS_, 128>>>(x, gamma, beta);
    qkv_gemm_kernel<<<dim3(12, 128), 256>>>(w_qkv);
    cudaFuncSetAttribute(attn_kernel, cudaFuncAttributeMaxDynamicSharedMemorySize,
                         (int)ATTN_SMEM);
    attn_kernel<<<dim3(32, 64), 256, ATTN_SMEM>>>();
    proj_gemm_kernel<<<dim3(4, 128), 256>>>(w_proj, b_proj, out);
}

// round 3
// speedup vs baseline: 1.0007x; 1.0007x over previous
#include <cuda_runtime.h>

#define B_    8
#define N_    2048
#define D_    512
#define H_    8
#define DH_   64
#define ROWS_ (B_ * N_)   // 16384

// Scratch (device globals — no allocations allowed in kernel_launch).
__device__ float g_xn[(size_t)ROWS_ * D_];   // LayerNorm output [16384, 512]
__device__ float g_q[(size_t)ROWS_ * D_];    // [b][h][n][dh]
__device__ float g_k[(size_t)ROWS_ * D_];    // [b][h][n][dh]
__device__ float g_v[(size_t)ROWS_ * D_];    // [b][h][n][dh]
__device__ float g_att[(size_t)ROWS_ * D_];  // attention out, [b][n][h*dh]

// ---------------------------------------------------------------------------
// LayerNorm: one row (512 floats) per 128-thread block, float4 per thread.
// ---------------------------------------------------------------------------
__global__ __launch_bounds__(128) void ln_kernel(const float* __restrict__ x,
                                                 const float* __restrict__ gamma,
                                                 const float* __restrict__ beta) {
    const int row = blockIdx.x;
    const int t = threadIdx.x;
    const float4 v = reinterpret_cast<const float4*>(x + (size_t)row * D_)[t];
    float s  = v.x + v.y + v.z + v.w;
    float ss = v.x * v.x + v.y * v.y + v.z * v.z + v.w * v.w;
#pragma unroll
    for (int o = 16; o; o >>= 1) {
        s  += __shfl_xor_sync(0xffffffffu, s, o);
        ss += __shfl_xor_sync(0xffffffffu, ss, o);
    }
    __shared__ float sh[4], sh2[4];
    if ((t & 31) == 0) { sh[t >> 5] = s; sh2[t >> 5] = ss; }
    __syncthreads();
    s  = sh[0] + sh[1] + sh[2] + sh[3];
    ss = sh2[0] + sh2[1] + sh2[2] + sh2[3];
    const float mean = s * (1.0f / D_);
    const float var  = ss * (1.0f / D_) - mean * mean;
    const float rstd = rsqrtf(var + 1e-6f);
    const float4 g4 = reinterpret_cast<const float4*>(gamma)[t];
    const float4 b4 = reinterpret_cast<const float4*>(beta)[t];
    float4 r;
    r.x = (v.x - mean) * rstd * g4.x + b4.x;
    r.y = (v.y - mean) * rstd * g4.y + b4.y;
    r.z = (v.z - mean) * rstd * g4.z + b4.z;
    r.w = (v.w - mean) * rstd * g4.w + b4.w;
    reinterpret_cast<float4*>(g_xn + (size_t)row * D_)[t] = r;
}

// ---------------------------------------------------------------------------
// QKV GEMM: C[16384,1536] = xn[16384,512] @ w_qkv[1536,512]^T
// 128x128x8 tiles, 256 threads, 8x8 microtile. Epilogue scatters into
// q/k/v in [b][h][n][dh] layout.
// ---------------------------------------------------------------------------
__global__ __launch_bounds__(256) void qkv_gemm_kernel(const float* __restrict__ W) {
    __shared__ __align__(16) float As[8 * 132];
    __shared__ __align__(16) float Ws[8 * 132];
    const int t  = threadIdx.x;
    const int bm = blockIdx.y * 128;
    const int bn = blockIdx.x * 128;
    const int ty = t >> 4, tx = t & 15;
    const int lr = t >> 1;          // load row 0..127
    const int ls = (t & 1) * 4;     // k offset 0 or 4
    const float* Ap = g_xn + (size_t)(bm + lr) * 512 + ls;
    const float* Wp = W + (size_t)(bn + lr) * 512 + ls;

    float acc[8][8];
#pragma unroll
    for (int i = 0; i < 8; i++)
#pragma unroll
        for (int j = 0; j < 8; j++) acc[i][j] = 0.0f;

    for (int k0 = 0; k0 < 512; k0 += 8) {
        const float4 av = *reinterpret_cast<const float4*>(Ap + k0);
        const float4 wv = *reinterpret_cast<const float4*>(Wp + k0);
        __syncthreads();
        As[(ls + 0) * 132 + lr] = av.x;
        As[(ls + 1) * 132 + lr] = av.y;
        As[(ls + 2) * 132 + lr] = av.z;
        As[(ls + 3) * 132 + lr] = av.w;
        Ws[(ls + 0) * 132 + lr] = wv.x;
        Ws[(ls + 1) * 132 + lr] = wv.y;
        Ws[(ls + 2) * 132 + lr] = wv.z;
        Ws[(ls + 3) * 132 + lr] = wv.w;
        __syncthreads();
#pragma unroll
        for (int k = 0; k < 8; k++) {
            const float4 a0 = *reinterpret_cast<const float4*>(&As[k * 132 + ty * 8]);
            const float4 a1 = *reinterpret_cast<const float4*>(&As[k * 132 + ty * 8 + 4]);
            const float4 b0 = *reinterpret_cast<const float4*>(&Ws[k * 132 + tx * 8]);
            const float4 b1 = *reinterpret_cast<const float4*>(&Ws[k * 132 + tx * 8 + 4]);
            const float a[8] = {a0.x, a0.y, a0.z, a0.w, a1.x, a1.y, a1.z, a1.w};
            const float b[8] = {b0.x, b0.y, b0.z, b0.w, b1.x, b1.y, b1.z, b1.w};
#pragma unroll
            for (int i = 0; i < 8; i++)
#pragma unroll
                for (int j = 0; j < 8; j++) acc[i][j] += a[i] * b[j];
        }
    }

    // epilogue: whole block lives in one of q/k/v (128 | 512)
    const int which = bn >> 9;
    float* dst = (which == 0) ? g_q : ((which == 1) ? g_k : g_v);
    const int cb = (bn & 511) + tx * 8;   // column within the 512-wide segment
    const int h  = cb >> 6;
    const int d0 = cb & 63;               // multiple of 8 -> two float4 stores
#pragma unroll
    for (int i = 0; i < 8; i++) {
        const int m = bm + ty * 8 + i;
        const int b = m >> 11, n = m & 2047;
        float* p = dst + ((size_t)(b * H_ + h) * N_ + n) * DH_ + d0;
        *reinterpret_cast<float4*>(p) =
            make_float4(acc[i][0], acc[i][1], acc[i][2], acc[i][3]);
        *reinterpret_cast<float4*>(p + 4) =
            make_float4(acc[i][4], acc[i][5], acc[i][6], acc[i][7]);
    }
}

// ---------------------------------------------------------------------------
// Flash attention: grid (32 q-tiles, 64 bh), 256 threads, Br=Bc=64, Dh=64.
// Q, K, P tiles stored TRANSPOSED (reduction-dim-major) with XOR swizzle
//   addr(r, c) = r*64 + (c ^ (r & 28))
// so both microtile operands of the two inner GEMM loops are LDS.128.
// Stores land with <=2-way bank conflicts; loads are chunk permutations
// (conflict-free / broadcast).
// ---------------------------------------------------------------------------
#define SWI(r, c) ((r) * 64 + ((c) ^ ((r) & 28)))
#define ATTN_SMEM (4 * 64 * 64 * sizeof(float))   // Qt + Kt + V + Pt = 64 KB

__global__ __launch_bounds__(256) void attn_kernel() {
    extern __shared__ __align__(16) float sm[];
    float* Qs = sm;               // [d][m] swizzled, 64x64
    float* Ks = Qs + 64 * 64;     // [d][n] swizzled, 64x64
    float* Vs = Ks + 64 * 64;     // [c][d] row-major, 64x64
    float* Ps = Vs + 64 * 64;     // [c][m] swizzled, 64x64

    const int t  = threadIdx.x;
    const int ty = t >> 4, tx = t & 15;   // 16x16 thread grid, 4x4 microtile
    const int ty4 = ty * 4, tx4 = tx * 4;
    const int bh = blockIdx.y;
    const int q0 = blockIdx.x * 64;
    const float* Qg = g_q + (size_t)bh * N_ * DH_;
    const float* Kg = g_k + (size_t)bh * N_ * DH_;
    const float* Vg = g_v + (size_t)bh * N_ * DH_;

    // load Q tile, store transposed+swizzled: Qt[d][m]
#pragma unroll
    for (int it = 0; it < 4; it++) {
        const int i = t + it * 256;
        const int r = i >> 4, c4 = (i & 15) << 2;   // r = m, c4 = d base
        const float4 qv = *reinterpret_cast<const float4*>(Qg + (size_t)(q0 + r) * DH_ + c4);
        Qs[SWI(c4 + 0, r)] = qv.x;
        Qs[SWI(c4 + 1, r)] = qv.y;
        Qs[SWI(c4 + 2, r)] = qv.z;
        Qs[SWI(c4 + 3, r)] = qv.w;
    }

    float m_r[4], l_r[4], O[4][4];
#pragma unroll
    for (int i = 0; i < 4; i++) {
        m_r[i] = -1e30f; l_r[i] = 0.0f;
#pragma unroll
        for (int j = 0; j < 4; j++) O[i][j] = 0.0f;
    }
    __syncthreads();

    for (int kt = 0; kt < 32; kt++) {
        // load K transposed+swizzled, V row-major
#pragma unroll
        for (int it = 0; it < 4; it++) {
            const int i = t + it * 256;
            const int r = i >> 4, c4 = (i & 15) << 2;
            const float4 kv = *reinterpret_cast<const float4*>(Kg + (size_t)(kt * 64 + r) * DH_ + c4);
            Ks[SWI(c4 + 0, r)] = kv.x;
            Ks[SWI(c4 + 1, r)] = kv.y;
            Ks[SWI(c4 + 2, r)] = kv.z;
            Ks[SWI(c4 + 3, r)] = kv.w;
            const float4 vv = *reinterpret_cast<const float4*>(Vg + (size_t)(kt * 64 + r) * DH_ + c4);
            *reinterpret_cast<float4*>(Vs + r * 64 + c4) = vv;
        }
        __syncthreads();

        // S = Q K^T : both operands LDS.128 from transposed tiles
        float s[4][4];
#pragma unroll
        for (int i = 0; i < 4; i++)
#pragma unroll
            for (int j = 0; j < 4; j++) s[i][j] = 0.0f;
#pragma unroll 8
        for (int d = 0; d < 64; d++) {
            const float4 a4 = *reinterpret_cast<const float4*>(Qs + SWI(d, ty4));
            const float4 b4 = *reinterpret_cast<const float4*>(Ks + SWI(d, tx4));
            const float a[4] = {a4.x, a4.y, a4.z, a4.w};
            const float b[4] = {b4.x, b4.y, b4.z, b4.w};
#pragma unroll
            for (int i = 0; i < 4; i++)
#pragma unroll
                for (int j = 0; j < 4; j++) s[i][j] += a[i] * b[j];
        }
#pragma unroll
        for (int i = 0; i < 4; i++)
#pragma unroll
            for (int j = 0; j < 4; j++) s[i][j] *= 0.125f;

        // online softmax; rows ty4..+3 shared across 16 lanes (shfl group)
        float alpha[4];
#pragma unroll
        for (int i = 0; i < 4; i++) {
            float mx = fmaxf(fmaxf(s[i][0], s[i][1]), fmaxf(s[i][2], s[i][3]));
#pragma unroll
            for (int o = 8; o; o >>= 1) mx = fmaxf(mx, __shfl_xor_sync(0xffffffffu, mx, o));
            const float mn = fmaxf(m_r[i], mx);
            float rs = 0.0f;
#pragma unroll
            for (int j = 0; j < 4; j++) {
                const float p = __expf(s[i][j] - mn);
                s[i][j] = p;
                rs += p;
            }
#pragma unroll
            for (int o = 8; o; o >>= 1) rs += __shfl_xor_sync(0xffffffffu, rs, o);
            const float al = __expf(m_r[i] - mn);
            l_r[i] = l_r[i] * al + rs;
            m_r[i] = mn;
            alpha[i] = al;
        }

        // store P transposed+swizzled: Pt[c=n][m], STS.128 per column j
#pragma unroll
        for (int j = 0; j < 4; j++) {
            *reinterpret_cast<float4*>(Ps + SWI(tx4 + j, ty4)) =
                make_float4(s[0][j], s[1][j], s[2][j], s[3][j]);
        }
        __syncthreads();

        // O = O*alpha + P V : both operands LDS.128
#pragma unroll
        for (int i = 0; i < 4; i++)
#pragma unroll
            for (int j = 0; j < 4; j++) O[i][j] *= alpha[i];
#pragma unroll 8
        for (int c = 0; c < 64; c++) {
            const float4 p4 = *reinterpret_cast<const float4*>(Ps + SWI(c, ty4));
            const float4 v4 = *reinterpret_cast<const float4*>(Vs + c * 64 + tx4);
            const float p[4] = {p4.x, p4.y, p4.z, p4.w};
            const float v[4] = {v4.x, v4.y, v4.z, v4.w};
#pragma unroll
            for (int i = 0; i < 4; i++)
#pragma unroll
                for (int j = 0; j < 4; j++) O[i][j] += p[i] * v[j];
        }
        __syncthreads();
    }

    // normalize and write to g_att [b][n][h*64 + d]
    const int b = bh >> 3, h = bh & 7;
#pragma unroll
    for (int i = 0; i < 4; i++) {
        const float inv = 1.0f / l_r[i];
        const int n = q0 + ty4 + i;
        const float4 o4 = make_float4(O[i][0] * inv, O[i][1] * inv,
                                      O[i][2] * inv, O[i][3] * inv);
        *reinterpret_cast<float4*>(g_att + ((size_t)(b * N_ + n)) * D_ + h * DH_ + tx4) = o4;
    }
}

// ---------------------------------------------------------------------------
// Output projection: out[16384,512] = g_att @ w_proj[512,512]^T + b_proj
// ---------------------------------------------------------------------------
__global__ __launch_bounds__(256) void proj_gemm_kernel(const float* __restrict__ W,
                                                        const float* __restrict__ bias,
                                                        float* __restrict__ C) {
    __shared__ __align__(16) float As[8 * 132];
    __shared__ __align__(16) float Ws[8 * 132];
    const int t  = threadIdx.x;
    const int bm = blockIdx.y * 128;
    const int bn = blockIdx.x * 128;
    const int ty = t >> 4, tx = t & 15;
    const int lr = t >> 1;
    const int ls = (t & 1) * 4;
    const float* Ap = g_att + (size_t)(bm + lr) * 512 + ls;
    const float* Wp = W + (size_t)(bn + lr) * 512 + ls;

    float acc[8][8];
#pragma unroll
    for (int i = 0; i < 8; i++)
#pragma unroll
        for (int j = 0; j < 8; j++) acc[i][j] = 0.0f;

    for (int k0 = 0; k0 < 512; k0 += 8) {
        const float4 av = *reinterpret_cast<const float4*>(Ap + k0);
        const float4 wv = *reinterpret_cast<const float4*>(Wp + k0);
        __syncthreads();
        As[(ls + 0) * 132 + lr] = av.x;
        As[(ls + 1) * 132 + lr] = av.y;
        As[(ls + 2) * 132 + lr] = av.z;
        As[(ls + 3) * 132 + lr] = av.w;
        Ws[(ls + 0) * 132 + lr] = wv.x;
        Ws[(ls + 1) * 132 + lr] = wv.y;
        Ws[(ls + 2) * 132 + lr] = wv.z;
        Ws[(ls + 3) * 132 + lr] = wv.w;
        __syncthreads();
#pragma unroll
        for (int k = 0; k < 8; k++) {
            const float4 a0 = *reinterpret_cast<const float4*>(&As[k * 132 + ty * 8]);
            const float4 a1 = *reinterpret_cast<const float4*>(&As[k * 132 + ty * 8 + 4]);
            const float4 b0 = *reinterpret_cast<const float4*>(&Ws[k * 132 + tx * 8]);
            const float4 b1 = *reinterpret_cast<const float4*>(&Ws[k * 132 + tx * 8 + 4]);
            const float a[8] = {a0.x, a0.y, a0.z, a0.w, a1.x, a1.y, a1.z, a1.w};
            const float b[8] = {b0.x, b0.y, b0.z, b0.w, b1.x, b1.y, b1.z, b1.w};
#pragma unroll
            for (int i = 0; i < 8; i++)
#pragma unroll
                for (int j = 0; j < 8; j++) acc[i][j] += a[i] * b[j];
        }
    }

    const int c0 = bn + tx * 8;
    const float4 bs0 = *reinterpret_cast<const float4*>(bias + c0);
    const float4 bs1 = *reinterpret_cast<const float4*>(bias + c0 + 4);
#pragma unroll
    for (int i = 0; i < 8; i++) {
        const int m = bm + ty * 8 + i;
        float* p = C + (size_t)m * 512 + c0;
        *reinterpret_cast<float4*>(p) =
            make_float4(acc[i][0] + bs0.x, acc[i][1] + bs0.y,
                        acc[i][2] + bs0.z, acc[i][3] + bs0.w);
        *reinterpret_cast<float4*>(p + 4) =
            make_float4(acc[i][4] + bs1.x, acc[i][5] + bs1.y,
                        acc[i][6] + bs1.z, acc[i][7] + bs1.w);
    }
}

// ---------------------------------------------------------------------------
extern "C" void kernel_launch(void* const* d_in, const int* in_sizes, int n_in,
                              void* d_out, int out_size) {
    const float* x      = (const float*)d_in[0];
    const float* w_qkv  = (const float*)d_in[1];
    const float* w_proj = (const float*)d_in[2];
    const float* b_proj = (const float*)d_in[3];
    const float* gamma  = (const float*)d_in[4];
    const float* beta   = (const float*)d_in[5];
    float* out = (float*)d_out;

    ln_kernel<<<ROWS_, 128>>>(x, gamma, beta);
    qkv_gemm_kernel<<<dim3(12, 128), 256>>>(w_qkv);
    cudaFuncSetAttribute(attn_kernel, cudaFuncAttributeMaxDynamicSharedMemorySize,
                         (int)ATTN_SMEM);
    attn_kernel<<<dim3(32, 64), 256, ATTN_SMEM>>>();
    proj_gemm_kernel<<<dim3(4, 128), 256>>>(w_proj, b_proj, out);
}

// round 9
// speedup vs baseline: 2.6417x; 2.6398x over previous
#include <cuda_runtime.h>
#include <stdint.h>

#define B_    8
#define N_    2048
#define D_    512
#define H_    8
#define DH_   64
#define ROWS_ (B_ * N_)

__device__ float g_xn[(size_t)ROWS_ * D_];
__device__ float g_q[(size_t)ROWS_ * D_];    // [b][h][n][dh]
__device__ float g_k[(size_t)ROWS_ * D_];
__device__ float g_v[(size_t)ROWS_ * D_];
__device__ float g_att[(size_t)ROWS_ * D_];  // [b][n][h*dh]

// ---- helpers ---------------------------------------------------------------
__device__ __forceinline__ uint32_t smem_u32(const void* p) {
    uint32_t a;
    asm("{ .reg .u64 t; cvta.to.shared.u64 t, %1; cvt.u32.u64 %0, t; }" : "=r"(a) : "l"(p));
    return a;
}
// packed bf16x2 of (a -> low, b -> high) via truncation
__device__ __forceinline__ uint32_t hi2(float a, float b) {
    return (__float_as_uint(a) >> 16) | (__float_as_uint(b) & 0xFFFF0000u);
}
__device__ __forceinline__ float hif(float a) {   // truncated-bf16 value as float
    return __uint_as_float(__float_as_uint(a) & 0xFFFF0000u);
}
__device__ __forceinline__ float ex2(float x) {
    float r; asm("ex2.approx.ftz.f32 %0, %1;" : "=f"(r) : "f"(x)); return r;
}
__device__ __forceinline__ void ldm4(uint32_t* r, uint32_t a) {
    asm volatile("ldmatrix.sync.aligned.m8n8.x4.shared.b16 {%0,%1,%2,%3}, [%4];"
                 : "=r"(r[0]), "=r"(r[1]), "=r"(r[2]), "=r"(r[3]) : "r"(a));
}
__device__ __forceinline__ void ldm4t(uint32_t* r, uint32_t a) {
    asm volatile("ldmatrix.sync.aligned.m8n8.x4.trans.shared.b16 {%0,%1,%2,%3}, [%4];"
                 : "=r"(r[0]), "=r"(r[1]), "=r"(r[2]), "=r"(r[3]) : "r"(a));
}
__device__ __forceinline__ void mm(float* c, const uint32_t* a, uint32_t b0, uint32_t b1) {
    asm volatile("mma.sync.aligned.m16n8k16.row.col.f32.bf16.bf16.f32 "
                 "{%0,%1,%2,%3},{%4,%5,%6,%7},{%8,%9},{%0,%1,%2,%3};"
                 : "+f"(c[0]), "+f"(c[1]), "+f"(c[2]), "+f"(c[3])
                 : "r"(a[0]), "r"(a[1]), "r"(a[2]), "r"(a[3]), "r"(b0), "r"(b1));
}

// ---- LayerNorm -------------------------------------------------------------
__global__ __launch_bounds__(128) void ln_kernel(const float* __restrict__ x,
                                                 const float* __restrict__ gamma,
                                                 const float* __restrict__ beta) {
    const int row = blockIdx.x, t = threadIdx.x;
    const float4 v = reinterpret_cast<const float4*>(x + (size_t)row * D_)[t];
    float s = v.x + v.y + v.z + v.w;
    float ss = v.x * v.x + v.y * v.y + v.z * v.z + v.w * v.w;
#pragma unroll
    for (int o = 16; o; o >>= 1) {
        s += __shfl_xor_sync(~0u, s, o);
        ss += __shfl_xor_sync(~0u, ss, o);
    }
    __shared__ float sh[4], sh2[4];
    if ((t & 31) == 0) { sh[t >> 5] = s; sh2[t >> 5] = ss; }
    __syncthreads();
    s = sh[0] + sh[1] + sh[2] + sh[3];
    ss = sh2[0] + sh2[1] + sh2[2] + sh2[3];
    const float mean = s * (1.0f / D_);
    const float rstd = rsqrtf(ss * (1.0f / D_) - mean * mean + 1e-6f);
    const float4 g4 = reinterpret_cast<const float4*>(gamma)[t];
    const float4 b4 = reinterpret_cast<const float4*>(beta)[t];
    float4 r;
    r.x = (v.x - mean) * rstd * g4.x + b4.x;
    r.y = (v.y - mean) * rstd * g4.y + b4.y;
    r.z = (v.z - mean) * rstd * g4.z + b4.z;
    r.w = (v.w - mean) * rstd * g4.w + b4.w;
    reinterpret_cast<float4*>(g_xn + (size_t)row * D_)[t] = r;
}

// ---- mma.sync GEMM: C[.,N] = A[16384,512] @ W[N,512]^T, 3x bf16 split ------
// 128x128 tile, BK=32, 256 thr / 8 warps (2x4), warp tile 64x32.
// SMEM (u32): Ah[128*16] Al Bh Bl -> 8192 u32 = 32 KB. Rows 64B, chunk^=(row&3).
__global__ __launch_bounds__(256) void gemm_mma(const float* __restrict__ Bw,
                                                const float* __restrict__ bias,
                                                float* __restrict__ outp, int mode) {
    __shared__ uint32_t sm[8192];
    const uint32_t sb = smem_u32(sm);
    const float* A = mode ? g_att : g_xn;
    const int t = threadIdx.x, lane = t & 31, wid = t >> 5;
    const int wr = wid >> 2, wc = wid & 3;
    const int bm = blockIdx.y * 128, bn = blockIdx.x * 128;

    float acc[4][4][4];
#pragma unroll
    for (int i = 0; i < 4; i++)
#pragma unroll
        for (int j = 0; j < 4; j++)
#pragma unroll
            for (int q = 0; q < 4; q++) acc[i][j][q] = 0.0f;

    for (int k0 = 0; k0 < 512; k0 += 32) {
        __syncthreads();
#pragma unroll
        for (int it = 0; it < 4; it++) {
            const int i = t + it * 256;          // 0..1023
            const int r = i >> 3, c4 = (i & 7) * 4;
            const int p = c4 >> 1;               // even pair index
            const int idx = r * 16 + (((p >> 2) ^ (r & 3)) << 2) + (p & 3);
            const float4 va = *(const float4*)(A + (size_t)(bm + r) * 512 + k0 + c4);
            sm[idx]        = hi2(va.x, va.y);
            sm[idx + 1]    = hi2(va.z, va.w);
            sm[2048 + idx]     = hi2(va.x - hif(va.x), va.y - hif(va.y));
            sm[2048 + idx + 1] = hi2(va.z - hif(va.z), va.w - hif(va.w));
            const float4 vb = *(const float4*)(Bw + (size_t)(bn + r) * 512 + k0 + c4);
            sm[4096 + idx]     = hi2(vb.x, vb.y);
            sm[4096 + idx + 1] = hi2(vb.z, vb.w);
            sm[6144 + idx]     = hi2(vb.x - hif(vb.x), vb.y - hif(vb.y));
            sm[6144 + idx + 1] = hi2(vb.z - hif(vb.z), vb.w - hif(vb.w));
        }
        __syncthreads();
#pragma unroll
        for (int ks = 0; ks < 2; ks++) {
            uint32_t bh[2][4], bl[2][4];
#pragma unroll
            for (int np = 0; np < 2; np++) {
                const int row = 32 * wc + 16 * np + (lane & 15);
                const int ch = (ks * 2 + (lane >> 4)) ^ (row & 3);
                ldm4(bh[np], sb + 16384 + row * 64 + ch * 16);
                ldm4(bl[np], sb + 24576 + row * 64 + ch * 16);
            }
#pragma unroll
            for (int mi = 0; mi < 4; mi++) {
                uint32_t ah[4], al[4];
                const int row = 64 * wr + 16 * mi + (lane & 15);
                const int ch = (ks * 2 + (lane >> 4)) ^ (row & 3);
                ldm4(ah, sb + row * 64 + ch * 16);
                ldm4(al, sb + 8192 + row * 64 + ch * 16);
#pragma unroll
                for (int np = 0; np < 2; np++) {
                    mm(acc[mi][2 * np],     ah, bh[np][0], bh[np][2]);
                    mm(acc[mi][2 * np],     ah, bl[np][0], bl[np][2]);
                    mm(acc[mi][2 * np],     al, bh[np][0], bh[np][2]);
                    mm(acc[mi][2 * np + 1], ah, bh[np][1], bh[np][3]);
                    mm(acc[mi][2 * np + 1], ah, bl[np][1], bl[np][3]);
                    mm(acc[mi][2 * np + 1], al, bh[np][1], bh[np][3]);
                }
            }
        }
    }
    // epilogue
#pragma unroll
    for (int mi = 0; mi < 4; mi++) {
#pragma unroll
        for (int ni = 0; ni < 4; ni++) {
            const int cg = bn + 32 * wc + 8 * ni + (lane & 3) * 2;
            const int m0 = bm + 64 * wr + 16 * mi + (lane >> 2);
            if (mode == 0) {
                const int which = cg >> 9, cbn = cg & 511;
                float* dst = which == 0 ? g_q : (which == 1 ? g_k : g_v);
                const int h = cbn >> 6, dd = cbn & 63;
                const int b0 = m0 >> 11, n0 = m0 & 2047;
                *(float2*)(dst + ((size_t)((b0 * H_ + h) * N_ + n0)) * DH_ + dd) =
                    make_float2(acc[mi][ni][0], acc[mi][ni][1]);
                const int m1 = m0 + 8, b1 = m1 >> 11, n1 = m1 & 2047;
                *(float2*)(dst + ((size_t)((b1 * H_ + h) * N_ + n1)) * DH_ + dd) =
                    make_float2(acc[mi][ni][2], acc[mi][ni][3]);
            } else {
                const float bs0 = bias[cg], bs1 = bias[cg + 1];
                *(float2*)(outp + (size_t)m0 * 512 + cg) =
                    make_float2(acc[mi][ni][0] + bs0, acc[mi][ni][1] + bs1);
                *(float2*)(outp + (size_t)(m0 + 8) * 512 + cg) =
                    make_float2(acc[mi][ni][2] + bs0, acc[mi][ni][3] + bs1);
            }
        }
    }
}

// ---- mma.sync flash attention ----------------------------------------------
// grid (16 qtiles, 64 bh), 256 thr / 8 warps. CTA: 128 q rows; warp w: rows 16w.
// SMEM bytes: Qh 0 | Ql 16384 | Kh 32768 | Kl 40960 | Vh 49152 | Vl 57344 (64KB)
// bf16 tiles, 128B rows (64 bf16), chunk^=(row&7).
#define ATTN_SMEM 65536
__global__ __launch_bounds__(256) void attn_mma() {
    extern __shared__ uint32_t smA[];
    const uint32_t sb = smem_u32(smA);
    const int t = threadIdx.x, lane = t & 31, wid = t >> 5;
    const int bh = blockIdx.y, q0 = blockIdx.x * 128;
    const int b = bh >> 3, h = bh & 7;
    const float* Qg = g_q + (size_t)bh * N_ * DH_;
    const float* Kg = g_k + (size_t)bh * N_ * DH_;
    const float* Vg = g_v + (size_t)bh * N_ * DH_;

    // Q tile 128x64 -> Qh/Ql
#pragma unroll
    for (int it = 0; it < 8; it++) {
        const int i = t + it * 256;             // 0..2047
        const int r = i >> 4, c4 = (i & 15) * 4;
        const int p = c4 >> 1;
        const int idx = r * 32 + (((p >> 2) ^ (r & 7)) << 2) + (p & 3);
        const float4 v = *(const float4*)(Qg + (size_t)(q0 + r) * DH_ + c4);
        smA[idx]            = hi2(v.x, v.y);
        smA[idx + 1]        = hi2(v.z, v.w);
        smA[4096 + idx]     = hi2(v.x - hif(v.x), v.y - hif(v.y));
        smA[4096 + idx + 1] = hi2(v.z - hif(v.z), v.w - hif(v.w));
    }

    float oacc[8][4];
#pragma unroll
    for (int i = 0; i < 8; i++)
#pragma unroll
        for (int j = 0; j < 4; j++) oacc[i][j] = 0.0f;
    float m0r = -1e30f, m1r = -1e30f, l0 = 0.0f, l1 = 0.0f;
    const float CS = 0.125f * 1.44269504f;

    for (int kt = 0; kt < 32; kt++) {
        __syncthreads();
        // K,V tiles 64x64 -> Kh/Kl/Vh/Vl
#pragma unroll
        for (int it = 0; it < 4; it++) {
            const int i = t + it * 256;         // 0..1023
            const int r = i >> 4, c4 = (i & 15) * 4;
            const int p = c4 >> 1;
            const int idx = r * 32 + (((p >> 2) ^ (r & 7)) << 2) + (p & 3);
            const float4 kv = *(const float4*)(Kg + (size_t)(kt * 64 + r) * DH_ + c4);
            smA[8192 + idx]      = hi2(kv.x, kv.y);
            smA[8192 + idx + 1]  = hi2(kv.z, kv.w);
            smA[10240 + idx]     = hi2(kv.x - hif(kv.x), kv.y - hif(kv.y));
            smA[10240 + idx + 1] = hi2(kv.z - hif(kv.z), kv.w - hif(kv.w));
            const float4 vv = *(const float4*)(Vg + (size_t)(kt * 64 + r) * DH_ + c4);
            smA[12288 + idx]     = hi2(vv.x, vv.y);
            smA[12288 + idx + 1] = hi2(vv.z, vv.w);
            smA[14336 + idx]     = hi2(vv.x - hif(vv.x), vv.y - hif(vv.y));
            smA[14336 + idx + 1] = hi2(vv.z - hif(vv.z), vv.w - hif(vv.w));
        }
        __syncthreads();

        // S = Q K^T : warp rows 16*wid, 8 n-frags (64 keys), 4 k-chunks (dh)
        float sacc[8][4];
#pragma unroll
        for (int i = 0; i < 8; i++)
#pragma unroll
            for (int j = 0; j < 4; j++) sacc[i][j] = 0.0f;
#pragma unroll
        for (int kc = 0; kc < 4; kc++) {
            uint32_t ah[4], al[4];
            {
                const int row = 16 * wid + (lane & 15);
                const int ch = (kc * 2 + (lane >> 4)) ^ (row & 7);
                ldm4(ah, sb + row * 128 + ch * 16);
                ldm4(al, sb + 16384 + row * 128 + ch * 16);
            }
#pragma unroll
            for (int np = 0; np < 4; np++) {
                uint32_t kh[4], kl[4];
                const int row = 16 * np + (lane & 15);
                const int ch = (kc * 2 + (lane >> 4)) ^ (row & 7);
                ldm4(kh, sb + 32768 + row * 128 + ch * 16);
                ldm4(kl, sb + 40960 + row * 128 + ch * 16);
                mm(sacc[2 * np],     ah, kh[0], kh[2]);
                mm(sacc[2 * np],     ah, kl[0], kl[2]);
                mm(sacc[2 * np],     al, kh[0], kh[2]);
                mm(sacc[2 * np + 1], ah, kh[1], kh[3]);
                mm(sacc[2 * np + 1], ah, kl[1], kl[3]);
                mm(sacc[2 * np + 1], al, kh[1], kh[3]);
            }
        }

        // online softmax (log2 domain); rows r0 = 16*wid + lane>>2, r1 = r0+8
        float mx0 = -1e30f, mx1 = -1e30f;
#pragma unroll
        for (int ni = 0; ni < 8; ni++) {
            sacc[ni][0] *= CS; sacc[ni][1] *= CS; sacc[ni][2] *= CS; sacc[ni][3] *= CS;
            mx0 = fmaxf(mx0, fmaxf(sacc[ni][0], sacc[ni][1]));
            mx1 = fmaxf(mx1, fmaxf(sacc[ni][2], sacc[ni][3]));
        }
        mx0 = fmaxf(mx0, __shfl_xor_sync(~0u, mx0, 1));
        mx0 = fmaxf(mx0, __shfl_xor_sync(~0u, mx0, 2));
        mx1 = fmaxf(mx1, __shfl_xor_sync(~0u, mx1, 1));
        mx1 = fmaxf(mx1, __shfl_xor_sync(~0u, mx1, 2));
        const float mn0 = fmaxf(m0r, mx0), mn1 = fmaxf(m1r, mx1);
        const float al0 = ex2(m0r - mn0), al1 = ex2(m1r - mn1);
        m0r = mn0; m1r = mn1;
        float rs0 = 0.0f, rs1 = 0.0f;
#pragma unroll
        for (int ni = 0; ni < 8; ni++) {
            sacc[ni][0] = ex2(sacc[ni][0] - mn0); rs0 += sacc[ni][0];
            sacc[ni][1] = ex2(sacc[ni][1] - mn0); rs0 += sacc[ni][1];
            sacc[ni][2] = ex2(sacc[ni][2] - mn1); rs1 += sacc[ni][2];
            sacc[ni][3] = ex2(sacc[ni][3] - mn1); rs1 += sacc[ni][3];
        }
        rs0 += __shfl_xor_sync(~0u, rs0, 1); rs0 += __shfl_xor_sync(~0u, rs0, 2);
        rs1 += __shfl_xor_sync(~0u, rs1, 1); rs1 += __shfl_xor_sync(~0u, rs1, 2);
        l0 = l0 * al0 + rs0;
        l1 = l1 * al1 + rs1;
#pragma unroll
        for (int ni = 0; ni < 8; ni++) {
            oacc[ni][0] *= al0; oacc[ni][1] *= al0;
            oacc[ni][2] *= al1; oacc[ni][3] *= al1;
        }

        // O += P V : P frags straight from sacc (C-frag == A-frag layout)
#pragma unroll
        for (int kc = 0; kc < 4; kc++) {
            const float* s0 = sacc[2 * kc];
            const float* s1 = sacc[2 * kc + 1];
            uint32_t ph[4], pl[4];
            ph[0] = hi2(s0[0], s0[1]); ph[1] = hi2(s0[2], s0[3]);
            ph[2] = hi2(s1[0], s1[1]); ph[3] = hi2(s1[2], s1[3]);
            pl[0] = hi2(s0[0] - hif(s0[0]), s0[1] - hif(s0[1]));
            pl[1] = hi2(s0[2] - hif(s0[2]), s0[3] - hif(s0[3]));
            pl[2] = hi2(s1[0] - hif(s1[0]), s1[1] - hif(s1[1]));
            pl[3] = hi2(s1[2] - hif(s1[2]), s1[3] - hif(s1[3]));
#pragma unroll
            for (int np = 0; np < 4; np++) {
                uint32_t vh[4], vl[4];
                const int row = 16 * kc + (lane & 15);
                const int ch = (np * 2 + (lane >> 4)) ^ (row & 7);
                ldm4t(vh, sb + 49152 + row * 128 + ch * 16);
                ldm4t(vl, sb + 57344 + row * 128 + ch * 16);
                mm(oacc[2 * np],     ph, vh[0], vh[1]);
                mm(oacc[2 * np],     ph, vl[0], vl[1]);
                mm(oacc[2 * np],     pl, vh[0], vh[1]);
                mm(oacc[2 * np + 1], ph, vh[2], vh[3]);
                mm(oacc[2 * np + 1], ph, vl[2], vl[3]);
                mm(oacc[2 * np + 1], pl, vh[2], vh[3]);
            }
        }
    }

    const float i0 = 1.0f / l0, i1 = 1.0f / l1;
    const int r0 = q0 + 16 * wid + (lane >> 2);
    float* base0 = g_att + ((size_t)(b * N_ + r0)) * D_ + h * DH_;
    float* base1 = base0 + 8 * D_;
#pragma unroll
    for (int ni = 0; ni < 8; ni++) {
        const int col = 8 * ni + (lane & 3) * 2;
        *(float2*)(base0 + col) = make_float2(oacc[ni][0] * i0, oacc[ni][1] * i0);
        *(float2*)(base1 + col) = make_float2(oacc[ni][2] * i1, oacc[ni][3] * i1);
    }
}

// ---------------------------------------------------------------------------
extern "C" void kernel_launch(void* const* d_in, const int* in_sizes, int n_in,
                              void* d_out, int out_size) {
    const float* x      = (const float*)d_in[0];
    const float* w_qkv  = (const float*)d_in[1];
    const float* w_proj = (const float*)d_in[2];
    const float* b_proj = (const float*)d_in[3];
    const float* gamma  = (const float*)d_in[4];
    const float* beta   = (const float*)d_in[5];
    float* out = (float*)d_out;

    cudaFuncSetAttribute(attn_mma, cudaFuncAttributeMaxDynamicSharedMemorySize, ATTN_SMEM);

    ln_kernel<<<ROWS_, 128>>>(x, gamma, beta);
    gemm_mma<<<dim3(12, 128), 256>>>(w_qkv, nullptr, nullptr, 0);
    attn_mma<<<dim3(16, 64), 256, ATTN_SMEM>>>();
    gemm_mma<<<dim3(4, 128), 256>>>(w_proj, b_proj, out, 1);
}

// round 12
// speedup vs baseline: 3.3955x; 1.2853x over previous
#include <cuda_runtime.h>
#include <stdint.h>

#define B_    8
#define N_    2048
#define D_    512
#define H_    8
#define DH_   64
#define ROWS_ (B_ * N_)

// packed bf16 hi/lo scratch (u32 = 2 bf16). x/att: [row][256]. qkv: [b][h][n][32].
__device__ uint32_t g_xh[(size_t)ROWS_ * 256], g_xl[(size_t)ROWS_ * 256];
__device__ uint32_t g_qh[(size_t)ROWS_ * 256], g_ql[(size_t)ROWS_ * 256];
__device__ uint32_t g_kh[(size_t)ROWS_ * 256], g_kl[(size_t)ROWS_ * 256];
__device__ uint32_t g_vh[(size_t)ROWS_ * 256], g_vl[(size_t)ROWS_ * 256];
__device__ uint32_t g_ah[(size_t)ROWS_ * 256], g_al[(size_t)ROWS_ * 256];
__device__ uint32_t g_wqh[1536 * 256], g_wql[1536 * 256];
__device__ uint32_t g_wph[512 * 256],  g_wpl[512 * 256];

// ---- helpers ---------------------------------------------------------------
__device__ __forceinline__ uint32_t smem_u32(const void* p) {
    uint32_t a;
    asm("{ .reg .u64 t; cvta.to.shared.u64 t, %1; cvt.u32.u64 %0, t; }" : "=r"(a) : "l"(p));
    return a;
}
__device__ __forceinline__ uint32_t hi2(float a, float b) {
    return (__float_as_uint(a) >> 16) | (__float_as_uint(b) & 0xFFFF0000u);
}
__device__ __forceinline__ float hif(float a) {
    return __uint_as_float(__float_as_uint(a) & 0xFFFF0000u);
}
__device__ __forceinline__ float ex2(float x) {
    float r; asm("ex2.approx.ftz.f32 %0, %1;" : "=f"(r) : "f"(x)); return r;
}
__device__ __forceinline__ void ldm4(uint32_t* r, uint32_t a) {
    asm volatile("ldmatrix.sync.aligned.m8n8.x4.shared.b16 {%0,%1,%2,%3}, [%4];"
                 : "=r"(r[0]), "=r"(r[1]), "=r"(r[2]), "=r"(r[3]) : "r"(a));
}
__device__ __forceinline__ void ldm4t(uint32_t* r, uint32_t a) {
    asm volatile("ldmatrix.sync.aligned.m8n8.x4.trans.shared.b16 {%0,%1,%2,%3}, [%4];"
                 : "=r"(r[0]), "=r"(r[1]), "=r"(r[2]), "=r"(r[3]) : "r"(a));
}
__device__ __forceinline__ void mm(float* c, const uint32_t* a, uint32_t b0, uint32_t b1) {
    asm volatile("mma.sync.aligned.m16n8k16.row.col.f32.bf16.bf16.f32 "
                 "{%0,%1,%2,%3},{%4,%5,%6,%7},{%8,%9},{%0,%1,%2,%3};"
                 : "+f"(c[0]), "+f"(c[1]), "+f"(c[2]), "+f"(c[3])
                 : "r"(a[0]), "r"(a[1]), "r"(a[2]), "r"(a[3]), "r"(b0), "r"(b1));
}
__device__ __forceinline__ void cpa16(uint32_t dst, const uint32_t* src) {
    asm volatile("cp.async.cg.shared.global [%0], [%1], 16;"
                 :: "r"(dst), "l"(__cvta_generic_to_global(src)) : "memory");
}
#define CP_COMMIT() asm volatile("cp.async.commit_group;" ::: "memory")
#define CP_WAIT1()  asm volatile("cp.async.wait_group 1;" ::: "memory")
#define CP_WAIT0()  asm volatile("cp.async.wait_group 0;" ::: "memory")

// ---- weight split: float[2n] -> hi/lo u32[n] -------------------------------
__global__ __launch_bounds__(256) void cvt_kernel(const float* __restrict__ w,
                                                  uint32_t* __restrict__ h,
                                                  uint32_t* __restrict__ l, int n2) {
    const int i = blockIdx.x * 256 + threadIdx.x;
    if (i < n2) {
        const float2 v = reinterpret_cast<const float2*>(w)[i];
        h[i] = hi2(v.x, v.y);
        l[i] = hi2(v.x - hif(v.x), v.y - hif(v.y));
    }
}

// ---- LayerNorm -> packed hi/lo ---------------------------------------------
__global__ __launch_bounds__(128) void ln_kernel(const float* __restrict__ x,
                                                 const float* __restrict__ gamma,
                                                 const float* __restrict__ beta) {
    const int row = blockIdx.x, t = threadIdx.x;
    const float4 v = reinterpret_cast<const float4*>(x + (size_t)row * D_)[t];
    float s = v.x + v.y + v.z + v.w;
    float ss = v.x * v.x + v.y * v.y + v.z * v.z + v.w * v.w;
#pragma unroll
    for (int o = 16; o; o >>= 1) {
        s += __shfl_xor_sync(~0u, s, o);
        ss += __shfl_xor_sync(~0u, ss, o);
    }
    __shared__ float sh[4], sh2[4];
    if ((t & 31) == 0) { sh[t >> 5] = s; sh2[t >> 5] = ss; }
    __syncthreads();
    s = sh[0] + sh[1] + sh[2] + sh[3];
    ss = sh2[0] + sh2[1] + sh2[2] + sh2[3];
    const float mean = s * (1.0f / D_);
    const float rstd = rsqrtf(ss * (1.0f / D_) - mean * mean + 1e-6f);
    const float4 g4 = reinterpret_cast<const float4*>(gamma)[t];
    const float4 b4 = reinterpret_cast<const float4*>(beta)[t];
    const float r0 = (v.x - mean) * rstd * g4.x + b4.x;
    const float r1 = (v.y - mean) * rstd * g4.y + b4.y;
    const float r2 = (v.z - mean) * rstd * g4.z + b4.z;
    const float r3 = (v.w - mean) * rstd * g4.w + b4.w;
    const size_t o = (size_t)row * 256 + 2 * t;
    g_xh[o]     = hi2(r0, r1);
    g_xh[o + 1] = hi2(r2, r3);
    g_xl[o]     = hi2(r0 - hif(r0), r1 - hif(r1));
    g_xl[o + 1] = hi2(r2 - hif(r2), r3 - hif(r3));
}

// ---- mma.sync GEMM: 128x128 tile, BK=64, cp.async 2-stage ------------------
// stage (u32): Ah[4096] Al[4096] Bh[4096] Bl[4096]; rows 32 u32, ch^(r&7).
#define GEMM_SMEM 131072
__global__ __launch_bounds__(256) void gemm_mma(const uint32_t* __restrict__ Ah,
                                                const uint32_t* __restrict__ Al,
                                                const uint32_t* __restrict__ Bh,
                                                const uint32_t* __restrict__ Bl,
                                                const float* __restrict__ bias,
                                                float* __restrict__ outp, int mode) {
    extern __shared__ uint32_t smg[];
    const uint32_t sb = smem_u32(smg);
    const int t = threadIdx.x, lane = t & 31, wid = t >> 5;
    const int wr = wid >> 2, wc = wid & 3;
    const int bm = blockIdx.y * 128, bn = blockIdx.x * 128;

    auto issue = [&](int kc, int s) {
#pragma unroll
        for (int j = 0; j < 16; j++) {
            const int seg = t + j * 256, tile = seg >> 10, w = seg & 1023;
            const int r = w >> 3, ch = w & 7;
            const uint32_t didx = (uint32_t)(s * 16384 + tile * 4096 + r * 32 + ((ch ^ (r & 7)) << 2));
            const uint32_t* base = tile == 0 ? Ah : tile == 1 ? Al : tile == 2 ? Bh : Bl;
            const int grow = (tile < 2 ? bm : bn) + r;
            cpa16(sb + didx * 4, base + (size_t)grow * 256 + kc * 32 + ch * 4);
        }
        CP_COMMIT();
    };

    float acc[4][4][4];
#pragma unroll
    for (int i = 0; i < 4; i++)
#pragma unroll
        for (int j = 0; j < 4; j++)
#pragma unroll
            for (int q = 0; q < 4; q++) acc[i][j][q] = 0.0f;

    issue(0, 0);
    for (int kc = 0; kc < 8; kc++) {
        if (kc < 7) { issue(kc + 1, (kc + 1) & 1); CP_WAIT1(); }
        else CP_WAIT0();
        __syncthreads();
        const uint32_t st = sb + (uint32_t)(kc & 1) * 65536;
#pragma unroll
        for (int ks = 0; ks < 4; ks++) {
            uint32_t bhf[2][4], blf[2][4];
#pragma unroll
            for (int np = 0; np < 2; np++) {
                const int row = 32 * wc + 16 * np + (lane & 15);
                const int ch = (ks * 2 + (lane >> 4)) ^ (row & 7);
                const uint32_t off = (uint32_t)(row * 32 + (ch << 2)) * 4;
                ldm4(bhf[np], st + 32768 + off);
                ldm4(blf[np], st + 49152 + off);
            }
#pragma unroll
            for (int mi = 0; mi < 4; mi++) {
                uint32_t ahf[4], alf[4];
                const int row = 64 * wr + 16 * mi + (lane & 15);
                const int ch = (ks * 2 + (lane >> 4)) ^ (row & 7);
                const uint32_t off = (uint32_t)(row * 32 + (ch << 2)) * 4;
                ldm4(ahf, st + off);
                ldm4(alf, st + 16384 + off);
#pragma unroll
                for (int np = 0; np < 2; np++) {
                    mm(acc[mi][2 * np],     ahf, bhf[np][0], bhf[np][2]);
                    mm(acc[mi][2 * np],     ahf, blf[np][0], blf[np][2]);
                    mm(acc[mi][2 * np],     alf, bhf[np][0], bhf[np][2]);
                    mm(acc[mi][2 * np + 1], ahf, bhf[np][1], bhf[np][3]);
                    mm(acc[mi][2 * np + 1], ahf, blf[np][1], blf[np][3]);
                    mm(acc[mi][2 * np + 1], alf, bhf[np][1], bhf[np][3]);
                }
            }
        }
        __syncthreads();
    }
    // epilogue
#pragma unroll
    for (int mi = 0; mi < 4; mi++) {
#pragma unroll
        for (int ni = 0; ni < 4; ni++) {
            const int cg = bn + 32 * wc + 8 * ni + (lane & 3) * 2;
            const int m0 = bm + 64 * wr + 16 * mi + (lane >> 2);
            const float a0 = acc[mi][ni][0], a1 = acc[mi][ni][1];
            const float a2 = acc[mi][ni][2], a3 = acc[mi][ni][3];
            if (mode == 0) {
                const int which = cg >> 9, cbn = cg & 511;
                uint32_t* dh_ = which == 0 ? g_qh : which == 1 ? g_kh : g_vh;
                uint32_t* dl_ = which == 0 ? g_ql : which == 1 ? g_kl : g_vl;
                const int h = cbn >> 6, dd = cbn & 63;
                const int b0 = m0 >> 11, n0 = m0 & 2047;
                const size_t i0 = ((size_t)((b0 * H_ + h) * N_ + n0)) * 32 + (dd >> 1);
                dh_[i0] = hi2(a0, a1);
                dl_[i0] = hi2(a0 - hif(a0), a1 - hif(a1));
                const int m1 = m0 + 8, b1 = m1 >> 11, n1 = m1 & 2047;
                const size_t i1 = ((size_t)((b1 * H_ + h) * N_ + n1)) * 32 + (dd >> 1);
                dh_[i1] = hi2(a2, a3);
                dl_[i1] = hi2(a2 - hif(a2), a3 - hif(a3));
            } else {
                const float bs0 = bias[cg], bs1 = bias[cg + 1];
                *(float2*)(outp + (size_t)m0 * 512 + cg) = make_float2(a0 + bs0, a1 + bs1);
                *(float2*)(outp + (size_t)(m0 + 8) * 512 + cg) = make_float2(a2 + bs0, a3 + bs1);
            }
        }
    }
}

// ---- mma.sync flash attention, cp.async 2-stage K/V ------------------------
// SMEM (u32): Qh[4096] Ql[4096] | stage s: Kh[2048] Kl[2048] Vh[2048] Vl[2048]
#define ATTN_SMEM 98304
__global__ __launch_bounds__(256) void attn_mma() {
    extern __shared__ uint32_t sma[];
    const uint32_t sb = smem_u32(sma);
    const int t = threadIdx.x, lane = t & 31, wid = t >> 5;
    const int bh = blockIdx.y, q0 = blockIdx.x * 128;
    const int b = bh >> 3, h = bh & 7;
    const uint32_t* qh = g_qh + (size_t)bh * N_ * 32;
    const uint32_t* ql = g_ql + (size_t)bh * N_ * 32;
    const uint32_t* kh = g_kh + (size_t)bh * N_ * 32;
    const uint32_t* kl = g_kl + (size_t)bh * N_ * 32;
    const uint32_t* vh = g_vh + (size_t)bh * N_ * 32;
    const uint32_t* vl = g_vl + (size_t)bh * N_ * 32;

    // Q tiles (one group)
#pragma unroll
    for (int j = 0; j < 8; j++) {
        const int seg = t + j * 256, half = seg >> 10, w = seg & 1023;
        const int r = w >> 3, ch = w & 7;
        const uint32_t didx = (uint32_t)(half * 4096 + r * 32 + ((ch ^ (r & 7)) << 2));
        cpa16(sb + didx * 4, (half ? ql : qh) + (size_t)(q0 + r) * 32 + ch * 4);
    }
    CP_COMMIT();
    auto issue_kv = [&](int kt, int s) {
#pragma unroll
        for (int j = 0; j < 8; j++) {
            const int seg = t + j * 256, tile = seg >> 9, w = seg & 511;
            const int r = w >> 3, ch = w & 7;
            const uint32_t didx = (uint32_t)(8192 + s * 8192 + tile * 2048 + r * 32 + ((ch ^ (r & 7)) << 2));
            const uint32_t* base = tile == 0 ? kh : tile == 1 ? kl : tile == 2 ? vh : vl;
            cpa16(sb + didx * 4, base + (size_t)(kt * 64 + r) * 32 + ch * 4);
        }
        CP_COMMIT();
    };
    issue_kv(0, 0);

    float oacc[8][4];
#pragma unroll
    for (int i = 0; i < 8; i++)
#pragma unroll
        for (int j = 0; j < 4; j++) oacc[i][j] = 0.0f;
    float m0r = -1e30f, m1r = -1e30f, l0 = 0.0f, l1 = 0.0f;
    const float CS = 0.125f * 1.44269504f;

    for (int kt = 0; kt < 32; kt++) {
        if (kt < 31) { issue_kv(kt + 1, (kt + 1) & 1); CP_WAIT1(); }
        else CP_WAIT0();
        __syncthreads();
        const uint32_t st = sb + 32768 + (uint32_t)(kt & 1) * 32768;

        float sacc[8][4];
#pragma unroll
        for (int i = 0; i < 8; i++)
#pragma unroll
            for (int j = 0; j < 4; j++) sacc[i][j] = 0.0f;
#pragma unroll
        for (int kc = 0; kc < 4; kc++) {
            uint32_t ahf[4], alf[4];
            {
                const int row = 16 * wid + (lane & 15);
                const int ch = (kc * 2 + (lane >> 4)) ^ (row & 7);
                const uint32_t off = (uint32_t)(row * 32 + (ch << 2)) * 4;
                ldm4(ahf, sb + off);
                ldm4(alf, sb + 16384 + off);
            }
#pragma unroll
            for (int np = 0; np < 4; np++) {
                uint32_t khf[4], klf[4];
                const int row = 16 * np + (lane & 15);
                const int ch = (kc * 2 + (lane >> 4)) ^ (row & 7);
                const uint32_t off = (uint32_t)(row * 32 + (ch << 2)) * 4;
                ldm4(khf, st + off);
                ldm4(klf, st + 8192 + off);
                mm(sacc[2 * np],     ahf, khf[0], khf[2]);
                mm(sacc[2 * np],     ahf, klf[0], klf[2]);
                mm(sacc[2 * np],     alf, khf[0], khf[2]);
                mm(sacc[2 * np + 1], ahf, khf[1], khf[3]);
                mm(sacc[2 * np + 1], ahf, klf[1], klf[3]);
                mm(sacc[2 * np + 1], alf, khf[1], khf[3]);
            }
        }

        float mx0 = -1e30f, mx1 = -1e30f;
#pragma unroll
        for (int ni = 0; ni < 8; ni++) {
            sacc[ni][0] *= CS; sacc[ni][1] *= CS; sacc[ni][2] *= CS; sacc[ni][3] *= CS;
            mx0 = fmaxf(mx0, fmaxf(sacc[ni][0], sacc[ni][1]));
            mx1 = fmaxf(mx1, fmaxf(sacc[ni][2], sacc[ni][3]));
        }
        mx0 = fmaxf(mx0, __shfl_xor_sync(~0u, mx0, 1));
        mx0 = fmaxf(mx0, __shfl_xor_sync(~0u, mx0, 2));
        mx1 = fmaxf(mx1, __shfl_xor_sync(~0u, mx1, 1));
        mx1 = fmaxf(mx1, __shfl_xor_sync(~0u, mx1, 2));
        const float mn0 = fmaxf(m0r, mx0), mn1 = fmaxf(m1r, mx1);
        const float al0 = ex2(m0r - mn0), al1 = ex2(m1r - mn1);
        m0r = mn0; m1r = mn1;
        float rs0 = 0.0f, rs1 = 0.0f;
#pragma unroll
        for (int ni = 0; ni < 8; ni++) {
            sacc[ni][0] = ex2(sacc[ni][0] - mn0); rs0 += sacc[ni][0];
            sacc[ni][1] = ex2(sacc[ni][1] - mn0); rs0 += sacc[ni][1];
            sacc[ni][2] = ex2(sacc[ni][2] - mn1); rs1 += sacc[ni][2];
            sacc[ni][3] = ex2(sacc[ni][3] - mn1); rs1 += sacc[ni][3];
        }
        rs0 += __shfl_xor_sync(~0u, rs0, 1); rs0 += __shfl_xor_sync(~0u, rs0, 2);
        rs1 += __shfl_xor_sync(~0u, rs1, 1); rs1 += __shfl_xor_sync(~0u, rs1, 2);
        l0 = l0 * al0 + rs0;
        l1 = l1 * al1 + rs1;
#pragma unroll
        for (int ni = 0; ni < 8; ni++) {
            oacc[ni][0] *= al0; oacc[ni][1] *= al0;
            oacc[ni][2] *= al1; oacc[ni][3] *= al1;
        }

#pragma unroll
        for (int kc = 0; kc < 4; kc++) {
            const float* s0 = sacc[2 * kc];
            const float* s1 = sacc[2 * kc + 1];
            uint32_t ph[4], pl[4];
            ph[0] = hi2(s0[0], s0[1]); ph[1] = hi2(s0[2], s0[3]);
            ph[2] = hi2(s1[0], s1[1]); ph[3] = hi2(s1[2], s1[3]);
            pl[0] = hi2(s0[0] - hif(s0[0]), s0[1] - hif(s0[1]));
            pl[1] = hi2(s0[2] - hif(s0[2]), s0[3] - hif(s0[3]));
            pl[2] = hi2(s1[0] - hif(s1[0]), s1[1] - hif(s1[1]));
            pl[3] = hi2(s1[2] - hif(s1[2]), s1[3] - hif(s1[3]));
#pragma unroll
            for (int np = 0; np < 4; np++) {
                uint32_t vhf[4], vlf[4];
                const int row = 16 * kc + (lane & 15);
                const int ch = (np * 2 + (lane >> 4)) ^ (row & 7);
                const uint32_t off = (uint32_t)(row * 32 + (ch << 2)) * 4;
                ldm4t(vhf, st + 16384 + off);
                ldm4t(vlf, st + 24576 + off);
                mm(oacc[2 * np],     ph, vhf[0], vhf[1]);
                mm(oacc[2 * np],     ph, vlf[0], vlf[1]);
                mm(oacc[2 * np],     pl, vhf[0], vhf[1]);
                mm(oacc[2 * np + 1], ph, vhf[2], vhf[3]);
                mm(oacc[2 * np + 1], ph, vlf[2], vlf[3]);
                mm(oacc[2 * np + 1], pl, vhf[2], vhf[3]);
            }
        }
        __syncthreads();
    }

    const float i0 = 1.0f / l0, i1 = 1.0f / l1;
    const int r0 = q0 + 16 * wid + (lane >> 2);
    const size_t base0 = ((size_t)(b * N_ + r0)) * 256 + h * 32;
    const size_t base1 = base0 + 8 * 256;
#pragma unroll
    for (int ni = 0; ni < 8; ni++) {
        const int ci = (8 * ni + (lane & 3) * 2) >> 1;
        const float o0 = oacc[ni][0] * i0, o1 = oacc[ni][1] * i0;
        const float o2 = oacc[ni][2] * i1, o3 = oacc[ni][3] * i1;
        g_ah[base0 + ci] = hi2(o0, o1);
        g_al[base0 + ci] = hi2(o0 - hif(o0), o1 - hif(o1));
        g_ah[base1 + ci] = hi2(o2, o3);
        g_al[base1 + ci] = hi2(o2 - hif(o2), o3 - hif(o3));
    }
}

// ---------------------------------------------------------------------------
extern "C" void kernel_launch(void* const* d_in, const int* in_sizes, int n_in,
                              void* d_out, int out_size) {
    const float* x      = (const float*)d_in[0];
    const float* w_qkv  = (const float*)d_in[1];
    const float* w_proj = (const float*)d_in[2];
    const float* b_proj = (const float*)d_in[3];
    const float* gamma  = (const float*)d_in[4];
    const float* beta   = (const float*)d_in[5];
    float* out = (float*)d_out;

    cudaFuncSetAttribute(gemm_mma, cudaFuncAttributeMaxDynamicSharedMemorySize, GEMM_SMEM);
    cudaFuncSetAttribute(attn_mma, cudaFuncAttributeMaxDynamicSharedMemorySize, ATTN_SMEM);

    uint32_t *wqh, *wql, *wph, *wpl, *xh, *xl, *ah, *al;
    cudaGetSymbolAddress((void**)&wqh, g_wqh);
    cudaGetSymbolAddress((void**)&wql, g_wql);
    cudaGetSymbolAddress((void**)&wph, g_wph);
    cudaGetSymbolAddress((void**)&wpl, g_wpl);
    cudaGetSymbolAddress((void**)&xh, g_xh);
    cudaGetSymbolAddress((void**)&xl, g_xl);
    cudaGetSymbolAddress((void**)&ah, g_ah);
    cudaGetSymbolAddress((void**)&al, g_al);

    cvt_kernel<<<1536, 256>>>(w_qkv, wqh, wql, 1536 * 256);
    cvt_kernel<<<512, 256>>>(w_proj, wph, wpl, 512 * 256);
    ln_kernel<<<ROWS_, 128>>>(x, gamma, beta);
    gemm_mma<<<dim3(12, 128), 256, GEMM_SMEM>>>(xh, xl, wqh, wql, nullptr, nullptr, 0);
    attn_mma<<<dim3(16, 64), 256, ATTN_SMEM>>>();
    gemm_mma<<<dim3(4, 128), 256, GEMM_SMEM>>>(ah, al, wph, wpl, b_proj, out, 1);
}

// round 17
// speedup vs baseline: 3.5128x; 1.0345x over previous
#include <cuda_runtime.h>
#include <stdint.h>

#define B_    8
#define N_    2048
#define D_    512
#define H_    8
#define DH_   64
#define ROWS_ (B_ * N_)

// packed bf16 hi/lo scratch (u32 = 2 bf16). x/att: [row][256]. qkv: [b][h][n][32].
__device__ uint32_t g_xh[(size_t)ROWS_ * 256], g_xl[(size_t)ROWS_ * 256];
__device__ uint32_t g_qh[(size_t)ROWS_ * 256], g_ql[(size_t)ROWS_ * 256];
__device__ uint32_t g_kh[(size_t)ROWS_ * 256], g_kl[(size_t)ROWS_ * 256];
__device__ uint32_t g_vh[(size_t)ROWS_ * 256], g_vl[(size_t)ROWS_ * 256];
__device__ uint32_t g_ah[(size_t)ROWS_ * 256], g_al[(size_t)ROWS_ * 256];
__device__ uint32_t g_wqh[1536 * 256], g_wql[1536 * 256];
__device__ uint32_t g_wph[512 * 256],  g_wpl[512 * 256];

// ---- helpers ---------------------------------------------------------------
__device__ __forceinline__ uint32_t smem_u32(const void* p) {
    uint32_t a;
    asm("{ .reg .u64 t; cvta.to.shared.u64 t, %1; cvt.u32.u64 %0, t; }" : "=r"(a) : "l"(p));
    return a;
}
__device__ __forceinline__ uint32_t hi2(float a, float b) {
    return (__float_as_uint(a) >> 16) | (__float_as_uint(b) & 0xFFFF0000u);
}
__device__ __forceinline__ float hif(float a) {
    return __uint_as_float(__float_as_uint(a) & 0xFFFF0000u);
}
__device__ __forceinline__ float ex2(float x) {
    float r; asm("ex2.approx.ftz.f32 %0, %1;" : "=f"(r) : "f"(x)); return r;
}
__device__ __forceinline__ void ldm4(uint32_t* r, uint32_t a) {
    asm volatile("ldmatrix.sync.aligned.m8n8.x4.shared.b16 {%0,%1,%2,%3}, [%4];"
                 : "=r"(r[0]), "=r"(r[1]), "=r"(r[2]), "=r"(r[3]) : "r"(a));
}
__device__ __forceinline__ void ldm4t(uint32_t* r, uint32_t a) {
    asm volatile("ldmatrix.sync.aligned.m8n8.x4.trans.shared.b16 {%0,%1,%2,%3}, [%4];"
                 : "=r"(r[0]), "=r"(r[1]), "=r"(r[2]), "=r"(r[3]) : "r"(a));
}
__device__ __forceinline__ void mm(float* c, const uint32_t* a, uint32_t b0, uint32_t b1) {
    asm volatile("mma.sync.aligned.m16n8k16.row.col.f32.bf16.bf16.f32 "
                 "{%0,%1,%2,%3},{%4,%5,%6,%7},{%8,%9},{%0,%1,%2,%3};"
                 : "+f"(c[0]), "+f"(c[1]), "+f"(c[2]), "+f"(c[3])
                 : "r"(a[0]), "r"(a[1]), "r"(a[2]), "r"(a[3]), "r"(b0), "r"(b1));
}
__device__ __forceinline__ void cpa16(uint32_t dst, const uint32_t* src) {
    asm volatile("cp.async.cg.shared.global [%0], [%1], 16;"
                 :: "r"(dst), "l"(__cvta_generic_to_global(src)) : "memory");
}
#define CP_COMMIT() asm volatile("cp.async.commit_group;" ::: "memory")
#define CP_WAIT1()  asm volatile("cp.async.wait_group 1;" ::: "memory")
#define CP_WAIT0()  asm volatile("cp.async.wait_group 0;" ::: "memory")

// ---- weight split ----------------------------------------------------------
__global__ __launch_bounds__(256) void cvt_kernel(const float* __restrict__ w,
                                                  uint32_t* __restrict__ h,
                                                  uint32_t* __restrict__ l, int n2) {
    const int i = blockIdx.x * 256 + threadIdx.x;
    if (i < n2) {
        const float2 v = reinterpret_cast<const float2*>(w)[i];
        h[i] = hi2(v.x, v.y);
        l[i] = hi2(v.x - hif(v.x), v.y - hif(v.y));
    }
}

// ---- LayerNorm -> packed hi/lo ---------------------------------------------
__global__ __launch_bounds__(128) void ln_kernel(const float* __restrict__ x,
                                                 const float* __restrict__ gamma,
                                                 const float* __restrict__ beta) {
    const int row = blockIdx.x, t = threadIdx.x;
    const float4 v = reinterpret_cast<const float4*>(x + (size_t)row * D_)[t];
    float s = v.x + v.y + v.z + v.w;
    float ss = v.x * v.x + v.y * v.y + v.z * v.z + v.w * v.w;
#pragma unroll
    for (int o = 16; o; o >>= 1) {
        s += __shfl_xor_sync(~0u, s, o);
        ss += __shfl_xor_sync(~0u, ss, o);
    }
    __shared__ float sh[4], sh2[4];
    if ((t & 31) == 0) { sh[t >> 5] = s; sh2[t >> 5] = ss; }
    __syncthreads();
    s = sh[0] + sh[1] + sh[2] + sh[3];
    ss = sh2[0] + sh2[1] + sh2[2] + sh2[3];
    const float mean = s * (1.0f / D_);
    const float rstd = rsqrtf(ss * (1.0f / D_) - mean * mean + 1e-6f);
    const float4 g4 = reinterpret_cast<const float4*>(gamma)[t];
    const float4 b4 = reinterpret_cast<const float4*>(beta)[t];
    const float r0 = (v.x - mean) * rstd * g4.x + b4.x;
    const float r1 = (v.y - mean) * rstd * g4.y + b4.y;
    const float r2 = (v.z - mean) * rstd * g4.z + b4.z;
    const float r3 = (v.w - mean) * rstd * g4.w + b4.w;
    const size_t o = (size_t)row * 256 + 2 * t;
    g_xh[o]     = hi2(r0, r1);
    g_xh[o + 1] = hi2(r2, r3);
    g_xl[o]     = hi2(r0 - hif(r0), r1 - hif(r1));
    g_xl[o + 1] = hi2(r2 - hif(r2), r3 - hif(r3));
}

// ---- mma.sync GEMM: 128x64 tile, BK=64, 128 thr, 2 CTA/SM ------------------
// stage (u32): Ah[4096] Al[4096] Bh[2048] Bl[2048] = 12288 u32 = 48KB.
#define GEMM_SMEM 98304
__global__ __launch_bounds__(128, 2) void gemm_mma(const uint32_t* __restrict__ Ah,
                                                   const uint32_t* __restrict__ Al,
                                                   const uint32_t* __restrict__ Bh,
                                                   const uint32_t* __restrict__ Bl,
                                                   const float* __restrict__ bias,
                                                   float* __restrict__ outp, int mode) {
    extern __shared__ uint32_t smg[];
    const uint32_t sb = smem_u32(smg);
    const int t = threadIdx.x, lane = t & 31, wid = t >> 5;
    const int wr = wid >> 1, wc = wid & 1;        // 2x2 warps, warp tile 64x32
    const int bm = blockIdx.y * 128, bn = blockIdx.x * 64;

    auto issue = [&](int kc, int s) {
#pragma unroll
        for (int j = 0; j < 24; j++) {
            const int seg = t + j * 128;          // 0..3071 cpa16 segments
            int tile, w;
            if (seg < 2048) { tile = seg >> 10; w = seg & 1023; }
            else            { tile = 2 + ((seg - 2048) >> 9); w = (seg - 2048) & 511; }
            const int r = w >> 3, ch = w & 7;
            const int toff = tile == 0 ? 0 : tile == 1 ? 4096 : tile == 2 ? 8192 : 10240;
            const uint32_t didx = (uint32_t)(s * 12288 + toff + r * 32 + ((ch ^ (r & 7)) << 2));
            const uint32_t* base = tile == 0 ? Ah : tile == 1 ? Al : tile == 2 ? Bh : Bl;
            const int grow = (tile < 2 ? bm : bn) + r;
            cpa16(sb + didx * 4, base + (size_t)grow * 256 + kc * 32 + ch * 4);
        }
        CP_COMMIT();
    };

    float acc[4][4][4];
#pragma unroll
    for (int i = 0; i < 4; i++)
#pragma unroll
        for (int j = 0; j < 4; j++)
#pragma unroll
            for (int q = 0; q < 4; q++) acc[i][j][q] = 0.0f;

    issue(0, 0);
    for (int kc = 0; kc < 8; kc++) {
        if (kc < 7) { issue(kc + 1, (kc + 1) & 1); CP_WAIT1(); }
        else CP_WAIT0();
        __syncthreads();
        const uint32_t st = sb + (uint32_t)(kc & 1) * 49152;
#pragma unroll
        for (int ks = 0; ks < 4; ks++) {
            uint32_t bhf[2][4], blf[2][4];
#pragma unroll
            for (int np = 0; np < 2; np++) {
                const int row = 32 * wc + 16 * np + (lane & 15);
                const int ch = (ks * 2 + (lane >> 4)) ^ (row & 7);
                const uint32_t off = (uint32_t)(row * 32 + (ch << 2)) * 4;
                ldm4(bhf[np], st + 32768 + off);
                ldm4(blf[np], st + 40960 + off);
            }
#pragma unroll
            for (int mi = 0; mi < 4; mi++) {
                uint32_t ahf[4], alf[4];
                const int row = 64 * wr + 16 * mi + (lane & 15);
                const int ch = (ks * 2 + (lane >> 4)) ^ (row & 7);
                const uint32_t off = (uint32_t)(row * 32 + (ch << 2)) * 4;
                ldm4(ahf, st + off);
                ldm4(alf, st + 16384 + off);
#pragma unroll
                for (int np = 0; np < 2; np++) {
                    mm(acc[mi][2 * np],     ahf, bhf[np][0], bhf[np][2]);
                    mm(acc[mi][2 * np],     ahf, blf[np][0], blf[np][2]);
                    mm(acc[mi][2 * np],     alf, bhf[np][0], bhf[np][2]);
                    mm(acc[mi][2 * np + 1], ahf, bhf[np][1], bhf[np][3]);
                    mm(acc[mi][2 * np + 1], ahf, blf[np][1], blf[np][3]);
                    mm(acc[mi][2 * np + 1], alf, bhf[np][1], bhf[np][3]);
                }
            }
        }
        __syncthreads();
    }
    // epilogue
#pragma unroll
    for (int mi = 0; mi < 4; mi++) {
#pragma unroll
        for (int ni = 0; ni < 4; ni++) {
            const int cg = bn + 32 * wc + 8 * ni + (lane & 3) * 2;
            const int m0 = bm + 64 * wr + 16 * mi + (lane >> 2);
            const float a0 = acc[mi][ni][0], a1 = acc[mi][ni][1];
            const float a2 = acc[mi][ni][2], a3 = acc[mi][ni][3];
            if (mode == 0) {
                const int which = cg >> 9, cbn = cg & 511;
                uint32_t* dh_ = which == 0 ? g_qh : which == 1 ? g_kh : g_vh;
                uint32_t* dl_ = which == 0 ? g_ql : which == 1 ? g_kl : g_vl;
                const int h = cbn >> 6, dd = cbn & 63;
                const int b0 = m0 >> 11, n0 = m0 & 2047;
                const size_t i0 = ((size_t)((b0 * H_ + h) * N_ + n0)) * 32 + (dd >> 1);
                dh_[i0] = hi2(a0, a1);
                dl_[i0] = hi2(a0 - hif(a0), a1 - hif(a1));
                const int m1 = m0 + 8, b1 = m1 >> 11, n1 = m1 & 2047;
                const size_t i1 = ((size_t)((b1 * H_ + h) * N_ + n1)) * 32 + (dd >> 1);
                dh_[i1] = hi2(a2, a3);
                dl_[i1] = hi2(a2 - hif(a2), a3 - hif(a3));
            } else {
                const float bs0 = bias[cg], bs1 = bias[cg + 1];
                *(float2*)(outp + (size_t)m0 * 512 + cg) = make_float2(a0 + bs0, a1 + bs1);
                *(float2*)(outp + (size_t)(m0 + 8) * 512 + cg) = make_float2(a2 + bs0, a3 + bs1);
            }
        }
    }
}

// ---- mma.sync flash attention: 64 q-rows/CTA, 128 thr, 2 CTA/SM ------------
// SMEM (u32): Qh[2048] Ql[2048] | stage s: Kh/Kl/Vh/Vl[2048] each = 80KB total
#define ATTN_SMEM 81920
__global__ __launch_bounds__(128, 2) void attn_mma() {
    extern __shared__ uint32_t sma[];
    const uint32_t sb = smem_u32(sma);
    const int t = threadIdx.x, lane = t & 31, wid = t >> 5;
    const int bh = blockIdx.y, q0 = blockIdx.x * 64;
    const int b = bh >> 3, h = bh & 7;
    const uint32_t* qh = g_qh + (size_t)bh * N_ * 32;
    const uint32_t* ql = g_ql + (size_t)bh * N_ * 32;
    const uint32_t* kh = g_kh + (size_t)bh * N_ * 32;
    const uint32_t* kl = g_kl + (size_t)bh * N_ * 32;
    const uint32_t* vh = g_vh + (size_t)bh * N_ * 32;
    const uint32_t* vl = g_vl + (size_t)bh * N_ * 32;

    // Q tiles (64 rows, hi+lo): 1024 cpa16
#pragma unroll
    for (int j = 0; j < 8; j++) {
        const int seg = t + j * 128, half = seg >> 9, w = seg & 511;
        const int r = w >> 3, ch = w & 7;
        const uint32_t didx = (uint32_t)(half * 2048 + r * 32 + ((ch ^ (r & 7)) << 2));
        cpa16(sb + didx * 4, (half ? ql : qh) + (size_t)(q0 + r) * 32 + ch * 4);
    }
    CP_COMMIT();
    auto issue_kv = [&](int kt, int s) {
#pragma unroll
        for (int j = 0; j < 16; j++) {
            const int seg = t + j * 128, tile = seg >> 9, w = seg & 511;
            const int r = w >> 3, ch = w & 7;
            const uint32_t didx = (uint32_t)(4096 + s * 8192 + tile * 2048 + r * 32 + ((ch ^ (r & 7)) << 2));
            const uint32_t* base = tile == 0 ? kh : tile == 1 ? kl : tile == 2 ? vh : vl;
            cpa16(sb + didx * 4, base + (size_t)(kt * 64 + r) * 32 + ch * 4);
        }
        CP_COMMIT();
    };
    issue_kv(0, 0);

    float oacc[8][4];
#pragma unroll
    for (int i = 0; i < 8; i++)
#pragma unroll
        for (int j = 0; j < 4; j++) oacc[i][j] = 0.0f;
    float m0r = -1e30f, m1r = -1e30f, l0 = 0.0f, l1 = 0.0f;
    const float CS = 0.125f * 1.44269504f;

    for (int kt = 0; kt < 32; kt++) {
        if (kt < 31) { issue_kv(kt + 1, (kt + 1) & 1); CP_WAIT1(); }
        else CP_WAIT0();
        __syncthreads();
        const uint32_t st = sb + 16384 + (uint32_t)(kt & 1) * 32768;

        float sacc[8][4];
#pragma unroll
        for (int i = 0; i < 8; i++)
#pragma unroll
            for (int j = 0; j < 4; j++) sacc[i][j] = 0.0f;
#pragma unroll
        for (int kc = 0; kc < 4; kc++) {
            uint32_t ahf[4], alf[4];
            {
                const int row = 16 * wid + (lane & 15);
                const int ch = (kc * 2 + (lane >> 4)) ^ (row & 7);
                const uint32_t off = (uint32_t)(row * 32 + (ch << 2)) * 4;
                ldm4(ahf, sb + off);
                ldm4(alf, sb + 8192 + off);
            }
#pragma unroll
            for (int np = 0; np < 4; np++) {
                uint32_t khf[4], klf[4];
                const int row = 16 * np + (lane & 15);
                const int ch = (kc * 2 + (lane >> 4)) ^ (row & 7);
                const uint32_t off = (uint32_t)(row * 32 + (ch << 2)) * 4;
                ldm4(khf, st + off);
                ldm4(klf, st + 8192 + off);
                mm(sacc[2 * np],     ahf, khf[0], khf[2]);
                mm(sacc[2 * np],     ahf, klf[0], klf[2]);
                mm(sacc[2 * np],     alf, khf[0], khf[2]);
                mm(sacc[2 * np + 1], ahf, khf[1], khf[3]);
                mm(sacc[2 * np + 1], ahf, klf[1], klf[3]);
                mm(sacc[2 * np + 1], alf, khf[1], khf[3]);
            }
        }

        float mx0 = -1e30f, mx1 = -1e30f;
#pragma unroll
        for (int ni = 0; ni < 8; ni++) {
            sacc[ni][0] *= CS; sacc[ni][1] *= CS; sacc[ni][2] *= CS; sacc[ni][3] *= CS;
            mx0 = fmaxf(mx0, fmaxf(sacc[ni][0], sacc[ni][1]));
            mx1 = fmaxf(mx1, fmaxf(sacc[ni][2], sacc[ni][3]));
        }
        mx0 = fmaxf(mx0, __shfl_xor_sync(~0u, mx0, 1));
        mx0 = fmaxf(mx0, __shfl_xor_sync(~0u, mx0, 2));
        mx1 = fmaxf(mx1, __shfl_xor_sync(~0u, mx1, 1));
        mx1 = fmaxf(mx1, __shfl_xor_sync(~0u, mx1, 2));
        const float mn0 = fmaxf(m0r, mx0), mn1 = fmaxf(m1r, mx1);
        const float al0 = ex2(m0r - mn0), al1 = ex2(m1r - mn1);
        m0r = mn0; m1r = mn1;
        float rs0 = 0.0f, rs1 = 0.0f;
#pragma unroll
        for (int ni = 0; ni < 8; ni++) {
            sacc[ni][0] = ex2(sacc[ni][0] - mn0); rs0 += sacc[ni][0];
            sacc[ni][1] = ex2(sacc[ni][1] - mn0); rs0 += sacc[ni][1];
            sacc[ni][2] = ex2(sacc[ni][2] - mn1); rs1 += sacc[ni][2];
            sacc[ni][3] = ex2(sacc[ni][3] - mn1); rs1 += sacc[ni][3];
        }
        rs0 += __shfl_xor_sync(~0u, rs0, 1); rs0 += __shfl_xor_sync(~0u, rs0, 2);
        rs1 += __shfl_xor_sync(~0u, rs1, 1); rs1 += __shfl_xor_sync(~0u, rs1, 2);
        l0 = l0 * al0 + rs0;
        l1 = l1 * al1 + rs1;
#pragma unroll
        for (int ni = 0; ni < 8; ni++) {
            oacc[ni][0] *= al0; oacc[ni][1] *= al0;
            oacc[ni][2] *= al1; oacc[ni][3] *= al1;
        }

#pragma unroll
        for (int kc = 0; kc < 4; kc++) {
            const float* s0 = sacc[2 * kc];
            const float* s1 = sacc[2 * kc + 1];
            uint32_t ph[4], pl[4];
            ph[0] = hi2(s0[0], s0[1]); ph[1] = hi2(s0[2], s0[3]);
            ph[2] = hi2(s1[0], s1[1]); ph[3] = hi2(s1[2], s1[3]);
            pl[0] = hi2(s0[0] - hif(s0[0]), s0[1] - hif(s0[1]));
            pl[1] = hi2(s0[2] - hif(s0[2]), s0[3] - hif(s0[3]));
            pl[2] = hi2(s1[0] - hif(s1[0]), s1[1] - hif(s1[1]));
            pl[3] = hi2(s1[2] - hif(s1[2]), s1[3] - hif(s1[3]));
#pragma unroll
            for (int np = 0; np < 4; np++) {
                uint32_t vhf[4], vlf[4];
                const int row = 16 * kc + (lane & 15);
                const int ch = (np * 2 + (lane >> 4)) ^ (row & 7);
                const uint32_t off = (uint32_t)(row * 32 + (ch << 2)) * 4;
                ldm4t(vhf, st + 16384 + off);
                ldm4t(vlf, st + 24576 + off);
                mm(oacc[2 * np],     ph, vhf[0], vhf[1]);
                mm(oacc[2 * np],     ph, vlf[0], vlf[1]);
                mm(oacc[2 * np],     pl, vhf[0], vhf[1]);
                mm(oacc[2 * np + 1], ph, vhf[2], vhf[3]);
                mm(oacc[2 * np + 1], ph, vlf[2], vlf[3]);
                mm(oacc[2 * np + 1], pl, vhf[2], vhf[3]);
            }
        }
        __syncthreads();
    }

    const float i0 = 1.0f / l0, i1 = 1.0f / l1;
    const int r0 = q0 + 16 * wid + (lane >> 2);
    const size_t base0 = ((size_t)(b * N_ + r0)) * 256 + h * 32;
    const size_t base1 = base0 + 8 * 256;
#pragma unroll
    for (int ni = 0; ni < 8; ni++) {
        const int ci = (8 * ni + (lane & 3) * 2) >> 1;
        const float o0 = oacc[ni][0] * i0, o1 = oacc[ni][1] * i0;
        const float o2 = oacc[ni][2] * i1, o3 = oacc[ni][3] * i1;
        g_ah[base0 + ci] = hi2(o0, o1);
        g_al[base0 + ci] = hi2(o0 - hif(o0), o1 - hif(o1));
        g_ah[base1 + ci] = hi2(o2, o3);
        g_al[base1 + ci] = hi2(o2 - hif(o2), o3 - hif(o3));
    }
}

// ---------------------------------------------------------------------------
extern "C" void kernel_launch(void* const* d_in, const int* in_sizes, int n_in,
                              void* d_out, int out_size) {
    const float* x      = (const float*)d_in[0];
    const float* w_qkv  = (const float*)d_in[1];
    const float* w_proj = (const float*)d_in[2];
    const float* b_proj = (const float*)d_in[3];
    const float* gamma  = (const float*)d_in[4];
    const float* beta   = (const float*)d_in[5];
    float* out = (float*)d_out;

    cudaFuncSetAttribute(gemm_mma, cudaFuncAttributeMaxDynamicSharedMemorySize, GEMM_SMEM);
    cudaFuncSetAttribute(attn_mma, cudaFuncAttributeMaxDynamicSharedMemorySize, ATTN_SMEM);

    uint32_t *wqh, *wql, *wph, *wpl, *xh, *xl, *ah, *al;
    cudaGetSymbolAddress((void**)&wqh, g_wqh);
    cudaGetSymbolAddress((void**)&wql, g_wql);
    cudaGetSymbolAddress((void**)&wph, g_wph);
    cudaGetSymbolAddress((void**)&wpl, g_wpl);
    cudaGetSymbolAddress((void**)&xh, g_xh);
    cudaGetSymbolAddress((void**)&xl, g_xl);
    cudaGetSymbolAddress((void**)&ah, g_ah);
    cudaGetSymbolAddress((void**)&al, g_al);

    cvt_kernel<<<1536, 256>>>(w_qkv, wqh, wql, 1536 * 256);
    cvt_kernel<<<512, 256>>>(w_proj, wph, wpl, 512 * 256);
    ln_kernel<<<ROWS_, 128>>>(x, gamma, beta);
    gemm_mma<<<dim3(24, 128), 128, GEMM_SMEM>>>(xh, xl, wqh, wql, nullptr, nullptr, 0);
    attn_mma<<<dim3(32, 64), 128, ATTN_SMEM>>>();
    gemm_mma<<<dim3(8, 128), 128, GEMM_SMEM>>>(ah, al, wph, wpl, b_proj, out, 1);
}